// round 7
// baseline (speedup 1.0000x reference)
#include <cuda_runtime.h>
#include <cuda_fp16.h>
#include <math.h>
#include <cstdint>

// ---------------- problem constants ----------------
#define NNODES 8192
#define NEDGES 65536
#define DIN    768
#define DHID   768
#define H1N    8
#define H2N    1
#define NEG_SLOPE 0.2f
#define EPSV 1e-16f

// ---------------- scratch (device globals; no allocs allowed) ----------------
__device__ float  g_h1[(size_t)NNODES * (H1N * DHID)];     // x @ W1        [8192, 6144] fp32
__device__ float  g_h2[(size_t)NNODES * DHID];             // o1 @ W2       [8192, 768]  fp32
__device__ __half g_xh [(size_t)NNODES * DIN];             // x fp16
__device__ __half g_o1h[(size_t)NNODES * (H1N * DHID)];    // elu(agg1+b1) fp16 (GEMM2 A)
__device__ __half g_w1th[(size_t)(H1N * DHID) * DIN];      // W1^T fp16 [6144, 768]
__device__ __half g_w2th[(size_t)DHID * (H1N * DHID)];     // W2^T fp16 [768, 6144]
__device__ float g_as1[NNODES * H1N];
__device__ float g_ad1[NNODES * H1N];
__device__ float g_as2[NNODES * H2N];
__device__ float g_ad2[NNODES * H2N];
__device__ float g_alpha1[(size_t)NEDGES * H1N];
__device__ float g_alpha2[(size_t)NEDGES * H2N];
__device__ int   g_deg[NNODES];
__device__ int   g_cur[NNODES];
__device__ int   g_off[NNODES + 1];
__device__ int   g_eid[NEDGES];

// ---------------- helpers ----------------
__device__ __forceinline__ void cp16(unsigned dst, const void* src) {
    asm volatile("cp.async.cg.shared.global [%0], [%1], 16;" :: "r"(dst), "l"(src));
}
__device__ __forceinline__ uint32_t smem_u32(const void* p) {
    return (uint32_t)__cvta_generic_to_shared(p);
}

#define MMA_F16(d, a, b)                                                               \
    asm volatile(                                                                      \
        "mma.sync.aligned.m16n8k16.row.col.f32.f16.f16.f32 "                           \
        "{%0,%1,%2,%3},{%4,%5,%6,%7},{%8,%9},{%0,%1,%2,%3};"                           \
        : "+f"((d)[0]), "+f"((d)[1]), "+f"((d)[2]), "+f"((d)[3])                       \
        : "r"((a)[0]), "r"((a)[1]), "r"((a)[2]), "r"((a)[3]), "r"((b)[0]), "r"((b)[1]))

// ---------------- fp32 -> fp16 convert ----------------
__global__ void f2h_kernel(const float* __restrict__ in, __half* __restrict__ out, int n4) {
    int i = blockIdx.x * blockDim.x + threadIdx.x;
    if (i < n4) {
        float4 v = ((const float4*)in)[i];
        __half2 h0 = __floats2half2_rn(v.x, v.y);
        __half2 h1 = __floats2half2_rn(v.z, v.w);
        uint2 u;
        u.x = *(uint32_t*)&h0; u.y = *(uint32_t*)&h1;
        ((uint2*)out)[i] = u;
    }
}

// ---------------- transpose + fp16 convert: in [R,C] fp32 -> out [C,R] fp16 ----------------
__global__ void transpose_h_kernel(const float* __restrict__ in, __half* __restrict__ out,
                                   int R, int C)
{
    __shared__ float t[32][33];
    int bx = blockIdx.x * 32, by = blockIdx.y * 32;
#pragma unroll
    for (int i = 0; i < 4; i++)
        t[threadIdx.y + 8 * i][threadIdx.x] =
            in[(size_t)(by + threadIdx.y + 8 * i) * C + bx + threadIdx.x];
    __syncthreads();
#pragma unroll
    for (int i = 0; i < 4; i++)
        out[(size_t)(bx + threadIdx.y + 8 * i) * R + by + threadIdx.x] =
            __float2half_rn(t[threadIdx.x][threadIdx.y + 8 * i]);
}

// ---------------- CSR build ----------------
__global__ void zero_counts_kernel() {
    int i = blockIdx.x * blockDim.x + threadIdx.x;
    if (i < NNODES) { g_deg[i] = 0; g_cur[i] = 0; }
}
__global__ void count_kernel(const int* __restrict__ dst) {
    int e = blockIdx.x * blockDim.x + threadIdx.x;
    if (e < NEDGES) atomicAdd(&g_deg[dst[e]], 1);
}
__global__ void scan_kernel() {
    __shared__ int s[1024];
    int t = threadIdx.x;
    int base = t * 8;
    int local[8];
    int run = 0;
#pragma unroll
    for (int i = 0; i < 8; i++) { local[i] = run; run += g_deg[base + i]; }
    s[t] = run;
    __syncthreads();
    for (int o = 1; o < 1024; o <<= 1) {
        int v = (t >= o) ? s[t - o] : 0;
        __syncthreads();
        s[t] += v;
        __syncthreads();
    }
    int prev = (t == 0) ? 0 : s[t - 1];
#pragma unroll
    for (int i = 0; i < 8; i++) g_off[base + i] = prev + local[i];
    if (t == 1023) g_off[NNODES] = s[1023];
}
__global__ void scatter_kernel(const int* __restrict__ dst) {
    int e = blockIdx.x * blockDim.x + threadIdx.x;
    if (e < NEDGES) {
        int d = dst[e];
        int p = atomicAdd(&g_cur[d], 1);
        g_eid[g_off[d] + p] = e;
    }
}

// ---------------- fp16 tensor-core GEMM ----------------
// C[M,N] = A[M,K] @ Bt^T ; A [M,K] half row-major, Bt [N,K] half row-major (K contig).
// Block 256x128, 8 warps (4 along M x 2 along N), warp tile 64x64.
// K-tile 32, 3-stage cp.async pipeline, dynamic smem, stride-40 rows (conflict-free).
#define HSTR 40
#define HG_ASTG (256 * HSTR)               // halves per A stage (10240)
#define HG_BSTG (128 * HSTR)               // halves per B stage (5120)
#define HG_STG  (HG_ASTG + HG_BSTG)        // halves per stage  (15360)
#define HG_SMEM (3 * HG_STG * 2)           // bytes (92160)

__global__ void __launch_bounds__(256, 1)
hgemm(const __half* __restrict__ A, const __half* __restrict__ Bt,
      float* __restrict__ C, int K, int N)
{
    extern __shared__ __half hs[];

    const int tid = threadIdx.x, wid = tid >> 5, lane = tid & 31;
    const int bn = blockIdx.x, bm = blockIdx.y;
    const int wm = (wid & 3) * 64;        // warp M origin (0,64,128,192)
    const int wn = (wid >> 2) * 64;       // warp N origin (0,64)
    const int g = lane >> 2, tg = lane & 3;

    const __half* Ag = A + (size_t)(bm * 256) * K;
    const __half* Bg = Bt + (size_t)(bn * 128) * K;

    float acc[32][4] = {};                // [mi*8 + ni][4], mi 0..3, ni 0..7
    const int T = K / 32;

    auto load_tile = [&](int t) {
        int st = t % 3;
        __half* As = hs + st * HG_STG;
        __half* Bs = As + HG_ASTG;
        int k0 = t * 32;
        // A: 1024 16B-chunks (256 rows x 4), 4 per thread
#pragma unroll
        for (int i = 0; i < 4; i++) {
            int ch = tid + i * 256;
            int r = ch >> 2, c = ch & 3;
            cp16(smem_u32(&As[r * HSTR + c * 8]), Ag + (size_t)r * K + k0 + c * 8);
        }
        // B: 512 chunks (128 rows x 4), 2 per thread
#pragma unroll
        for (int i = 0; i < 2; i++) {
            int ch = tid + i * 256;
            int r = ch >> 2, c = ch & 3;
            cp16(smem_u32(&Bs[r * HSTR + c * 8]), Bg + (size_t)r * K + k0 + c * 8);
        }
        asm volatile("cp.async.commit_group;");
    };

    load_tile(0);
    if (T > 1) load_tile(1);

    for (int t = 0; t < T; t++) {
        asm volatile("cp.async.wait_group 1;");
        __syncthreads();
        if (t + 2 < T) load_tile(t + 2);

        const __half* Ab = hs + (t % 3) * HG_STG;
        const __half* Bb = Ab + HG_ASTG;
#pragma unroll
        for (int kc = 0; kc < 2; kc++) {
            uint32_t a[4][4], b[8][2];
#pragma unroll
            for (int mi = 0; mi < 4; mi++) {
                int base = (wm + mi * 16 + g) * HSTR + kc * 16 + 2 * tg;
                a[mi][0] = *(const uint32_t*)&Ab[base];
                a[mi][1] = *(const uint32_t*)&Ab[base + 8 * HSTR];
                a[mi][2] = *(const uint32_t*)&Ab[base + 8];
                a[mi][3] = *(const uint32_t*)&Ab[base + 8 * HSTR + 8];
            }
#pragma unroll
            for (int ni = 0; ni < 8; ni++) {
                int nb = (wn + ni * 8 + g) * HSTR + kc * 16 + 2 * tg;
                b[ni][0] = *(const uint32_t*)&Bb[nb];
                b[ni][1] = *(const uint32_t*)&Bb[nb + 8];
            }
#pragma unroll
            for (int mi = 0; mi < 4; mi++)
#pragma unroll
                for (int ni = 0; ni < 8; ni++)
                    MMA_F16(acc[mi * 8 + ni], a[mi], b[ni]);
        }
        __syncthreads();
    }

    // epilogue
#pragma unroll
    for (int mi = 0; mi < 4; mi++) {
        int r0 = bm * 256 + wm + mi * 16 + g;
#pragma unroll
        for (int ni = 0; ni < 8; ni++) {
            int c = bn * 128 + wn + ni * 8 + tg * 2;
            float* p = C + (size_t)r0 * N + c;
            *(float2*)p = make_float2(acc[mi * 8 + ni][0], acc[mi * 8 + ni][1]);
            *(float2*)(p + (size_t)8 * N) = make_float2(acc[mi * 8 + ni][2], acc[mi * 8 + ni][3]);
        }
    }
}

// ---------------- per-(node,head) attention coefficients ----------------
__global__ void alphas_kernel(const float* __restrict__ h,
                              const float* __restrict__ a_s, const float* __restrict__ a_d,
                              float* __restrict__ out_s, float* __restrict__ out_d,
                              int H, int C)
{
    int w = (blockIdx.x * blockDim.x + threadIdx.x) >> 5;
    int lane = threadIdx.x & 31;
    if (w >= NNODES * H) return;
    int n = w / H, hd = w % H;
    const float* hp  = h + (size_t)n * H * C + (size_t)hd * C;
    const float* asp = a_s + (size_t)hd * C;
    const float* adp = a_d + (size_t)hd * C;
    float ss = 0.f, sd = 0.f;
    for (int c = lane; c < C; c += 32) {
        float v = hp[c];
        ss += v * asp[c];
        sd += v * adp[c];
    }
#pragma unroll
    for (int o = 16; o; o >>= 1) {
        ss += __shfl_down_sync(0xffffffffu, ss, o);
        sd += __shfl_down_sync(0xffffffffu, sd, o);
    }
    if (lane == 0) { out_s[w] = ss; out_d[w] = sd; }
}

// ---------------- per-(dst,head) segment softmax ----------------
__global__ void softmax_kernel(const int* __restrict__ src,
                               const float* __restrict__ as, const float* __restrict__ ad,
                               float* __restrict__ alpha, int H)
{
    int idx = blockIdx.x * blockDim.x + threadIdx.x;
    if (idx >= NNODES * H) return;
    int d = idx / H, hd = idx % H;
    int s0 = g_off[d], s1 = g_off[d + 1];
    if (s0 == s1) return;
    float adv = ad[idx];

    float m = -1e30f;
    for (int i = s0; i < s1; i++) {
        int e = g_eid[i];
        float x = as[src[e] * H + hd] + adv;
        x = (x > 0.f) ? x : NEG_SLOPE * x;
        m = fmaxf(m, x);
    }
    float sum = 0.f;
    for (int i = s0; i < s1; i++) {
        int e = g_eid[i];
        float x = as[src[e] * H + hd] + adv;
        x = (x > 0.f) ? x : NEG_SLOPE * x;
        float w = __expf(x - m);
        alpha[(size_t)e * H + hd] = w;
        sum += w;
    }
    float inv = 1.f / (sum + EPSV);
    for (int i = s0; i < s1; i++) {
        int e = g_eid[i];
        alpha[(size_t)e * H + hd] *= inv;
    }
}

// ---------------- aggregation ----------------
// acc = sum_e alpha * h[src] + b; layer1 (do_elu): out_h = fp16(elu(acc)); layer2: out_f = acc.
__global__ void __launch_bounds__(192)
aggregate_kernel(const int* __restrict__ src, const float* __restrict__ alpha,
                 const float* __restrict__ h, float* __restrict__ out_f,
                 __half* __restrict__ out_h, const float* __restrict__ bias,
                 int H, int C, int do_elu)
{
    int d  = blockIdx.x / H;
    int hd = blockIdx.x % H;
    int t  = threadIdx.x;
    int s0 = g_off[d], s1 = g_off[d + 1];
    size_t rs = (size_t)H * C;

    float4 acc = make_float4(0.f, 0.f, 0.f, 0.f);
    for (int i = s0; i < s1; i++) {
        int e = g_eid[i];
        float a = alpha[(size_t)e * H + hd];
        float4 v = *(((const float4*)(h + (size_t)src[e] * rs + (size_t)hd * C)) + t);
        acc.x += a * v.x; acc.y += a * v.y; acc.z += a * v.z; acc.w += a * v.w;
    }
    float4 b = *(((const float4*)(bias + (size_t)hd * C)) + t);
    acc.x += b.x; acc.y += b.y; acc.z += b.z; acc.w += b.w;
    if (do_elu) {
        acc.x = (acc.x > 0.f) ? acc.x : expm1f(acc.x);
        acc.y = (acc.y > 0.f) ? acc.y : expm1f(acc.y);
        acc.z = (acc.z > 0.f) ? acc.z : expm1f(acc.z);
        acc.w = (acc.w > 0.f) ? acc.w : expm1f(acc.w);
        __half2 h0 = __floats2half2_rn(acc.x, acc.y);
        __half2 h1 = __floats2half2_rn(acc.z, acc.w);
        uint2 u; u.x = *(uint32_t*)&h0; u.y = *(uint32_t*)&h1;
        *(((uint2*)(out_h + (size_t)d * rs + (size_t)hd * C)) + t) = u;
    } else {
        *(((float4*)(out_f + (size_t)d * rs + (size_t)hd * C)) + t) = acc;
    }
}

// ---------------- launch ----------------
extern "C" void kernel_launch(void* const* d_in, const int* in_sizes, int n_in,
                              void* d_out, int out_size)
{
    const float* x    = (const float*)d_in[0];
    const float* W1   = (const float*)d_in[1];
    const float* a_s1 = (const float*)d_in[2];
    const float* a_d1 = (const float*)d_in[3];
    const float* b1   = (const float*)d_in[4];
    const float* W2   = (const float*)d_in[5];
    const float* a_s2 = (const float*)d_in[6];
    const float* a_d2 = (const float*)d_in[7];
    const float* b2   = (const float*)d_in[8];
    const int* edges  = (const int*)d_in[9];
    const int* src = edges;
    const int* dst = edges + NEDGES;
    float* out = (float*)d_out;

    float *h1, *h2, *as1, *ad1, *as2, *ad2, *al1, *al2;
    __half *xh, *o1h, *w1th, *w2th;
    cudaGetSymbolAddress((void**)&h1,   g_h1);
    cudaGetSymbolAddress((void**)&h2,   g_h2);
    cudaGetSymbolAddress((void**)&xh,   g_xh);
    cudaGetSymbolAddress((void**)&o1h,  g_o1h);
    cudaGetSymbolAddress((void**)&w1th, g_w1th);
    cudaGetSymbolAddress((void**)&w2th, g_w2th);
    cudaGetSymbolAddress((void**)&as1,  g_as1);
    cudaGetSymbolAddress((void**)&ad1,  g_ad1);
    cudaGetSymbolAddress((void**)&as2,  g_as2);
    cudaGetSymbolAddress((void**)&ad2,  g_ad2);
    cudaGetSymbolAddress((void**)&al1,  g_alpha1);
    cudaGetSymbolAddress((void**)&al2,  g_alpha2);

    cudaFuncSetAttribute(hgemm, cudaFuncAttributeMaxDynamicSharedMemorySize, HG_SMEM);

    dim3 tblk(32, 8);

    // 0: x -> fp16
    f2h_kernel<<<(NNODES * DIN / 4 + 255) / 256, 256>>>(x, xh, NNODES * DIN / 4);
    // 1: W1 [768,6144] -> W1^T fp16 [6144,768]
    {
        dim3 gt((H1N * DHID) / 32, DIN / 32);
        transpose_h_kernel<<<gt, tblk>>>(W1, w1th, DIN, H1N * DHID);
    }
    // 2: W2 [6144,768] -> W2^T fp16 [768,6144]
    {
        dim3 gt(DHID / 32, (H1N * DHID) / 32);
        transpose_h_kernel<<<gt, tblk>>>(W2, w2th, H1N * DHID, DHID);
    }
    // 3: GEMM1 (ncu capture slot)  h1 = x @ W1  [8192, 6144]
    {
        dim3 grid((H1N * DHID) / 128, NNODES / 256);   // (48, 32)
        hgemm<<<grid, 256, HG_SMEM>>>(xh, w1th, h1, DIN, H1N * DHID);
    }
    // CSR build
    zero_counts_kernel<<<(NNODES + 255) / 256, 256>>>();
    count_kernel<<<(NEDGES + 255) / 256, 256>>>(dst);
    scan_kernel<<<1, 1024>>>();
    scatter_kernel<<<(NEDGES + 255) / 256, 256>>>(dst);
    // layer-1 attention + aggregation (writes o1 as fp16)
    alphas_kernel<<<(NNODES * H1N * 32 + 255) / 256, 256>>>(h1, a_s1, a_d1, as1, ad1, H1N, DHID);
    softmax_kernel<<<(NNODES * H1N + 255) / 256, 256>>>(src, as1, ad1, al1, H1N);
    aggregate_kernel<<<NNODES * H1N, DHID / 4>>>(src, al1, h1, nullptr, o1h, b1, H1N, DHID, 1);
    // GEMM2  h2 = o1 @ W2  [8192, 768]
    {
        dim3 grid((H2N * DHID) / 128, NNODES / 256);   // (6, 32)
        hgemm<<<grid, 256, HG_SMEM>>>(o1h, w2th, h2, H1N * DHID, H2N * DHID);
    }
    // layer-2 attention + aggregation (fp32 out)
    alphas_kernel<<<(NNODES * H2N * 32 + 255) / 256, 256>>>(h2, a_s2, a_d2, as2, ad2, H2N, DHID);
    softmax_kernel<<<(NNODES * H2N + 255) / 256, 256>>>(src, as2, ad2, al2, H2N);
    aggregate_kernel<<<NNODES * H2N, DHID / 4>>>(src, al2, h2, out, nullptr, b2, H2N, DHID, 0);
}

// round 8
// speedup vs baseline: 1.1711x; 1.1711x over previous
#include <cuda_runtime.h>
#include <cuda_fp16.h>
#include <math.h>
#include <cstdint>

// ---------------- problem constants ----------------
#define NNODES 8192
#define NEDGES 65536
#define DIN    768
#define DHID   768
#define H1N    8
#define H2N    1
#define NEG_SLOPE 0.2f
#define EPSV 1e-16f

// ---------------- scratch (device globals; no allocs allowed) ----------------
__device__ float  g_h1[(size_t)NNODES * (H1N * DHID)];     // x @ W1        [8192, 6144] fp32
__device__ float  g_h2[(size_t)NNODES * DHID];             // o1 @ W2       [8192, 768]  fp32
__device__ __half g_xh [(size_t)NNODES * DIN];             // x fp16
__device__ __half g_o1h[(size_t)NNODES * (H1N * DHID)];    // elu(agg1+b1) fp16 (GEMM2 A)
__device__ __half g_w1th[(size_t)(H1N * DHID) * DIN];      // W1^T fp16 [6144, 768]
__device__ __half g_w2th[(size_t)DHID * (H1N * DHID)];     // W2^T fp16 [768, 6144]
__device__ float g_as1[NNODES * H1N];
__device__ float g_ad1[NNODES * H1N];
__device__ float g_as2[NNODES * H2N];
__device__ float g_ad2[NNODES * H2N];
__device__ float g_alpha1[(size_t)NEDGES * H1N];
__device__ float g_alpha2[(size_t)NEDGES * H2N];
__device__ int   g_deg[NNODES];
__device__ int   g_cur[NNODES];
__device__ int   g_off[NNODES + 1];
__device__ int   g_eid[NEDGES];

// ---------------- helpers ----------------
__device__ __forceinline__ void cp16(unsigned dst, const void* src) {
    asm volatile("cp.async.cg.shared.global [%0], [%1], 16;" :: "r"(dst), "l"(src));
}
__device__ __forceinline__ uint32_t smem_u32(const void* p) {
    return (uint32_t)__cvta_generic_to_shared(p);
}

#define MMA_F16(d, a, b)                                                               \
    asm volatile(                                                                      \
        "mma.sync.aligned.m16n8k16.row.col.f32.f16.f16.f32 "                           \
        "{%0,%1,%2,%3},{%4,%5,%6,%7},{%8,%9},{%0,%1,%2,%3};"                           \
        : "+f"((d)[0]), "+f"((d)[1]), "+f"((d)[2]), "+f"((d)[3])                       \
        : "r"((a)[0]), "r"((a)[1]), "r"((a)[2]), "r"((a)[3]), "r"((b)[0]), "r"((b)[1]))

#define LDSM_X4(r, addr)                                                               \
    asm volatile("ldmatrix.sync.aligned.m8n8.x4.shared.b16 {%0,%1,%2,%3}, [%4];"       \
        : "=r"((r)[0]), "=r"((r)[1]), "=r"((r)[2]), "=r"((r)[3]) : "r"(addr))

// ---------------- fp32 -> fp16 convert ----------------
__global__ void f2h_kernel(const float* __restrict__ in, __half* __restrict__ out, int n4) {
    int i = blockIdx.x * blockDim.x + threadIdx.x;
    if (i < n4) {
        float4 v = ((const float4*)in)[i];
        __half2 h0 = __floats2half2_rn(v.x, v.y);
        __half2 h1 = __floats2half2_rn(v.z, v.w);
        uint2 u;
        u.x = *(uint32_t*)&h0; u.y = *(uint32_t*)&h1;
        ((uint2*)out)[i] = u;
    }
}

// ---------------- transpose + fp16 convert: in [R,C] fp32 -> out [C,R] fp16 ----------------
__global__ void transpose_h_kernel(const float* __restrict__ in, __half* __restrict__ out,
                                   int R, int C)
{
    __shared__ float t[32][33];
    int bx = blockIdx.x * 32, by = blockIdx.y * 32;
#pragma unroll
    for (int i = 0; i < 4; i++)
        t[threadIdx.y + 8 * i][threadIdx.x] =
            in[(size_t)(by + threadIdx.y + 8 * i) * C + bx + threadIdx.x];
    __syncthreads();
#pragma unroll
    for (int i = 0; i < 4; i++)
        out[(size_t)(bx + threadIdx.y + 8 * i) * R + by + threadIdx.x] =
            __float2half_rn(t[threadIdx.x][threadIdx.y + 8 * i]);
}

// ---------------- CSR build ----------------
__global__ void zero_counts_kernel() {
    int i = blockIdx.x * blockDim.x + threadIdx.x;
    if (i < NNODES) { g_deg[i] = 0; g_cur[i] = 0; }
}
__global__ void count_kernel(const int* __restrict__ dst) {
    int e = blockIdx.x * blockDim.x + threadIdx.x;
    if (e < NEDGES) atomicAdd(&g_deg[dst[e]], 1);
}
__global__ void scan_kernel() {
    __shared__ int s[1024];
    int t = threadIdx.x;
    int base = t * 8;
    int local[8];
    int run = 0;
#pragma unroll
    for (int i = 0; i < 8; i++) { local[i] = run; run += g_deg[base + i]; }
    s[t] = run;
    __syncthreads();
    for (int o = 1; o < 1024; o <<= 1) {
        int v = (t >= o) ? s[t - o] : 0;
        __syncthreads();
        s[t] += v;
        __syncthreads();
    }
    int prev = (t == 0) ? 0 : s[t - 1];
#pragma unroll
    for (int i = 0; i < 8; i++) g_off[base + i] = prev + local[i];
    if (t == 1023) g_off[NNODES] = s[1023];
}
__global__ void scatter_kernel(const int* __restrict__ dst) {
    int e = blockIdx.x * blockDim.x + threadIdx.x;
    if (e < NEDGES) {
        int d = dst[e];
        int p = atomicAdd(&g_cur[d], 1);
        g_eid[g_off[d] + p] = e;
    }
}

// ---------------- fp16 tensor-core GEMM ----------------
// C[M,N] = A[M,K] @ Bt^T ; A [M,K] half row-major, Bt [N,K] half row-major (K contig).
// Block 128x128, 8 warps (2x4), warp tile 64x32.
// K-tile 32, 3-stage cp.async pipeline, ldmatrix fragment loads.
// smem row stride 40 halves (80B): cp.async stores and LDSM both conflict-free.
#define HSTR 40
#define HG_STG  (2 * 128 * HSTR)           // halves per stage (A + B) = 10240
#define HG_SMEM (3 * HG_STG * 2)           // bytes = 61440

__global__ void __launch_bounds__(256)
hgemm(const __half* __restrict__ A, const __half* __restrict__ Bt,
      float* __restrict__ C, int K, int N)
{
    extern __shared__ __half hs[];

    const int tid = threadIdx.x, wid = tid >> 5, lane = tid & 31;
    const int bn = blockIdx.x, bm = blockIdx.y;
    const int wm = (wid >> 2) * 64;       // warp M origin
    const int wn = (wid & 3) * 32;        // warp N origin
    const int g = lane >> 2, tg = lane & 3;

    const __half* Ag = A + (size_t)(bm * 128) * K;
    const __half* Bg = Bt + (size_t)(bn * 128) * K;

    float acc[16][4] = {};
    const int T = K / 32;

    auto load_tile = [&](int t) {
        int st = t % 3;
        __half* As = hs + st * HG_STG;
        __half* Bs = As + 128 * HSTR;
        int k0 = t * 32;
#pragma unroll
        for (int i = 0; i < 2; i++) {
            int ci = tid + i * 256;
            int r = ci >> 2, c = ci & 3;           // row 0..127, 16B-chunk 0..3
            cp16(smem_u32(&As[r * HSTR + c * 8]), Ag + (size_t)r * K + k0 + c * 8);
            cp16(smem_u32(&Bs[r * HSTR + c * 8]), Bg + (size_t)r * K + k0 + c * 8);
        }
        asm volatile("cp.async.commit_group;");
    };

    load_tile(0);
    if (T > 1) load_tile(1);

    // ldmatrix lane roles (shared by A and B x4 loads):
    //   A mi-tile:   row = wm + mi*16 + (lane & 15), khalf = kc*16 + (lane >> 4)*8
    //   B pair p:    row = wn + p*16  + (lane & 15), khalf = kc*16 + ((lane >> 3) & 1)*8
    const int a_r = lane & 15;
    const int a_k = (lane >> 4) * 8;
    const int b_r = ((lane >> 4) << 3) + (lane & 7);   // 0..7 for sel 0,1; 8..15 for sel 2,3
    const int b_k = ((lane >> 3) & 1) * 8;

    for (int t = 0; t < T; t++) {
        asm volatile("cp.async.wait_group 1;");
        __syncthreads();
        if (t + 2 < T) load_tile(t + 2);

        const __half* Ab = hs + (t % 3) * HG_STG;
        const __half* Bb = Ab + 128 * HSTR;
#pragma unroll
        for (int kc = 0; kc < 2; kc++) {
            uint32_t a[4][4], b[4][2];
#pragma unroll
            for (int mi = 0; mi < 4; mi++) {
                uint32_t ad = smem_u32(&Ab[(wm + mi * 16 + a_r) * HSTR + kc * 16 + a_k]);
                LDSM_X4(a[mi], ad);
            }
#pragma unroll
            for (int p = 0; p < 2; p++) {
                uint32_t br[4];
                uint32_t bd = smem_u32(&Bb[(wn + p * 16 + b_r) * HSTR + kc * 16 + b_k]);
                LDSM_X4(br, bd);
                b[2 * p][0] = br[0]; b[2 * p][1] = br[1];
                b[2 * p + 1][0] = br[2]; b[2 * p + 1][1] = br[3];
            }
#pragma unroll
            for (int mi = 0; mi < 4; mi++)
#pragma unroll
                for (int ni = 0; ni < 4; ni++)
                    MMA_F16(acc[mi * 4 + ni], a[mi], b[ni]);
        }
        __syncthreads();
    }

    // epilogue
#pragma unroll
    for (int mi = 0; mi < 4; mi++) {
        int r0 = bm * 128 + wm + mi * 16 + g;
#pragma unroll
        for (int ni = 0; ni < 4; ni++) {
            int c = bn * 128 + wn + ni * 8 + tg * 2;
            float* p = C + (size_t)r0 * N + c;
            *(float2*)p = make_float2(acc[mi * 4 + ni][0], acc[mi * 4 + ni][1]);
            *(float2*)(p + (size_t)8 * N) = make_float2(acc[mi * 4 + ni][2], acc[mi * 4 + ni][3]);
        }
    }
}

// ---------------- per-(node,head) attention coefficients ----------------
__global__ void alphas_kernel(const float* __restrict__ h,
                              const float* __restrict__ a_s, const float* __restrict__ a_d,
                              float* __restrict__ out_s, float* __restrict__ out_d,
                              int H, int C)
{
    int w = (blockIdx.x * blockDim.x + threadIdx.x) >> 5;
    int lane = threadIdx.x & 31;
    if (w >= NNODES * H) return;
    int n = w / H, hd = w % H;
    const float* hp  = h + (size_t)n * H * C + (size_t)hd * C;
    const float* asp = a_s + (size_t)hd * C;
    const float* adp = a_d + (size_t)hd * C;
    float ss = 0.f, sd = 0.f;
    for (int c = lane; c < C; c += 32) {
        float v = hp[c];
        ss += v * asp[c];
        sd += v * adp[c];
    }
#pragma unroll
    for (int o = 16; o; o >>= 1) {
        ss += __shfl_down_sync(0xffffffffu, ss, o);
        sd += __shfl_down_sync(0xffffffffu, sd, o);
    }
    if (lane == 0) { out_s[w] = ss; out_d[w] = sd; }
}

// ---------------- per-(dst,head) segment softmax ----------------
__global__ void softmax_kernel(const int* __restrict__ src,
                               const float* __restrict__ as, const float* __restrict__ ad,
                               float* __restrict__ alpha, int H)
{
    int idx = blockIdx.x * blockDim.x + threadIdx.x;
    if (idx >= NNODES * H) return;
    int d = idx / H, hd = idx % H;
    int s0 = g_off[d], s1 = g_off[d + 1];
    if (s0 == s1) return;
    float adv = ad[idx];

    float m = -1e30f;
    for (int i = s0; i < s1; i++) {
        int e = g_eid[i];
        float x = as[src[e] * H + hd] + adv;
        x = (x > 0.f) ? x : NEG_SLOPE * x;
        m = fmaxf(m, x);
    }
    float sum = 0.f;
    for (int i = s0; i < s1; i++) {
        int e = g_eid[i];
        float x = as[src[e] * H + hd] + adv;
        x = (x > 0.f) ? x : NEG_SLOPE * x;
        float w = __expf(x - m);
        alpha[(size_t)e * H + hd] = w;
        sum += w;
    }
    float inv = 1.f / (sum + EPSV);
    for (int i = s0; i < s1; i++) {
        int e = g_eid[i];
        alpha[(size_t)e * H + hd] *= inv;
    }
}

// ---------------- aggregation ----------------
// acc = sum_e alpha * h[src] + b; layer1 (do_elu): out_h = fp16(elu(acc)); layer2: out_f = acc.
__global__ void __launch_bounds__(192)
aggregate_kernel(const int* __restrict__ src, const float* __restrict__ alpha,
                 const float* __restrict__ h, float* __restrict__ out_f,
                 __half* __restrict__ out_h, const float* __restrict__ bias,
                 int H, int C, int do_elu)
{
    int d  = blockIdx.x / H;
    int hd = blockIdx.x % H;
    int t  = threadIdx.x;
    int s0 = g_off[d], s1 = g_off[d + 1];
    size_t rs = (size_t)H * C;

    float4 acc = make_float4(0.f, 0.f, 0.f, 0.f);
    for (int i = s0; i < s1; i++) {
        int e = g_eid[i];
        float a = alpha[(size_t)e * H + hd];
        float4 v = *(((const float4*)(h + (size_t)src[e] * rs + (size_t)hd * C)) + t);
        acc.x += a * v.x; acc.y += a * v.y; acc.z += a * v.z; acc.w += a * v.w;
    }
    float4 b = *(((const float4*)(bias + (size_t)hd * C)) + t);
    acc.x += b.x; acc.y += b.y; acc.z += b.z; acc.w += b.w;
    if (do_elu) {
        acc.x = (acc.x > 0.f) ? acc.x : expm1f(acc.x);
        acc.y = (acc.y > 0.f) ? acc.y : expm1f(acc.y);
        acc.z = (acc.z > 0.f) ? acc.z : expm1f(acc.z);
        acc.w = (acc.w > 0.f) ? acc.w : expm1f(acc.w);
        __half2 h0 = __floats2half2_rn(acc.x, acc.y);
        __half2 h1 = __floats2half2_rn(acc.z, acc.w);
        uint2 u; u.x = *(uint32_t*)&h0; u.y = *(uint32_t*)&h1;
        *(((uint2*)(out_h + (size_t)d * rs + (size_t)hd * C)) + t) = u;
    } else {
        *(((float4*)(out_f + (size_t)d * rs + (size_t)hd * C)) + t) = acc;
    }
}

// ---------------- launch ----------------
extern "C" void kernel_launch(void* const* d_in, const int* in_sizes, int n_in,
                              void* d_out, int out_size)
{
    const float* x    = (const float*)d_in[0];
    const float* W1   = (const float*)d_in[1];
    const float* a_s1 = (const float*)d_in[2];
    const float* a_d1 = (const float*)d_in[3];
    const float* b1   = (const float*)d_in[4];
    const float* W2   = (const float*)d_in[5];
    const float* a_s2 = (const float*)d_in[6];
    const float* a_d2 = (const float*)d_in[7];
    const float* b2   = (const float*)d_in[8];
    const int* edges  = (const int*)d_in[9];
    const int* src = edges;
    const int* dst = edges + NEDGES;
    float* out = (float*)d_out;

    float *h1, *h2, *as1, *ad1, *as2, *ad2, *al1, *al2;
    __half *xh, *o1h, *w1th, *w2th;
    cudaGetSymbolAddress((void**)&h1,   g_h1);
    cudaGetSymbolAddress((void**)&h2,   g_h2);
    cudaGetSymbolAddress((void**)&xh,   g_xh);
    cudaGetSymbolAddress((void**)&o1h,  g_o1h);
    cudaGetSymbolAddress((void**)&w1th, g_w1th);
    cudaGetSymbolAddress((void**)&w2th, g_w2th);
    cudaGetSymbolAddress((void**)&as1,  g_as1);
    cudaGetSymbolAddress((void**)&ad1,  g_ad1);
    cudaGetSymbolAddress((void**)&as2,  g_as2);
    cudaGetSymbolAddress((void**)&ad2,  g_ad2);
    cudaGetSymbolAddress((void**)&al1,  g_alpha1);
    cudaGetSymbolAddress((void**)&al2,  g_alpha2);

    cudaFuncSetAttribute(hgemm, cudaFuncAttributeMaxDynamicSharedMemorySize, HG_SMEM);

    dim3 tblk(32, 8);

    // 0: x -> fp16
    f2h_kernel<<<(NNODES * DIN / 4 + 255) / 256, 256>>>(x, xh, NNODES * DIN / 4);
    // 1: W1 [768,6144] -> W1^T fp16 [6144,768]
    {
        dim3 gt((H1N * DHID) / 32, DIN / 32);
        transpose_h_kernel<<<gt, tblk>>>(W1, w1th, DIN, H1N * DHID);
    }
    // 2: W2 [6144,768] -> W2^T fp16 [768,6144]
    {
        dim3 gt(DHID / 32, (H1N * DHID) / 32);
        transpose_h_kernel<<<gt, tblk>>>(W2, w2th, H1N * DHID, DHID);
    }
    // 3: GEMM1 (ncu capture slot)  h1 = x @ W1  [8192, 6144]
    {
        dim3 grid((H1N * DHID) / 128, NNODES / 128);   // (48, 64)
        hgemm<<<grid, 256, HG_SMEM>>>(xh, w1th, h1, DIN, H1N * DHID);
    }
    // CSR build
    zero_counts_kernel<<<(NNODES + 255) / 256, 256>>>();
    count_kernel<<<(NEDGES + 255) / 256, 256>>>(dst);
    scan_kernel<<<1, 1024>>>();
    scatter_kernel<<<(NEDGES + 255) / 256, 256>>>(dst);
    // layer-1 attention + aggregation (writes o1 as fp16)
    alphas_kernel<<<(NNODES * H1N * 32 + 255) / 256, 256>>>(h1, a_s1, a_d1, as1, ad1, H1N, DHID);
    softmax_kernel<<<(NNODES * H1N + 255) / 256, 256>>>(src, as1, ad1, al1, H1N);
    aggregate_kernel<<<NNODES * H1N, DHID / 4>>>(src, al1, h1, nullptr, o1h, b1, H1N, DHID, 1);
    // GEMM2  h2 = o1 @ W2  [8192, 768]
    {
        dim3 grid((H2N * DHID) / 128, NNODES / 128);   // (6, 64)
        hgemm<<<grid, 256, HG_SMEM>>>(o1h, w2th, h2, H1N * DHID, H2N * DHID);
    }
    // layer-2 attention + aggregation (fp32 out)
    alphas_kernel<<<(NNODES * H2N * 32 + 255) / 256, 256>>>(h2, a_s2, a_d2, as2, ad2, H2N, DHID);
    softmax_kernel<<<(NNODES * H2N + 255) / 256, 256>>>(src, as2, ad2, al2, H2N);
    aggregate_kernel<<<NNODES * H2N, DHID / 4>>>(src, al2, h2, out, nullptr, b2, H2N, DHID, 0);
}

// round 9
// speedup vs baseline: 1.3010x; 1.1109x over previous
#include <cuda_runtime.h>
#include <cuda_fp16.h>
#include <math.h>
#include <cstdint>

// ---------------- problem constants ----------------
#define NNODES 8192
#define NEDGES 65536
#define DIN    768
#define DHID   768
#define H1N    8
#define H2N    1
#define NEG_SLOPE 0.2f
#define EPSV 1e-16f

// ---------------- scratch (device globals; no allocs allowed) ----------------
__device__ float  g_h1[(size_t)NNODES * (H1N * DHID)];     // x @ W1        [8192, 6144] fp32
__device__ float  g_h2[(size_t)NNODES * DHID];             // o1 @ W2       [8192, 768]  fp32
__device__ __half g_xh [(size_t)NNODES * DIN];             // x fp16
__device__ __half g_o1h[(size_t)NNODES * (H1N * DHID)];    // elu(agg1+b1) fp16 (GEMM2 A)
__device__ __half g_w1th[(size_t)(H1N * DHID) * DIN];      // W1^T fp16 [6144, 768]
__device__ __half g_w2th[(size_t)DHID * (H1N * DHID)];     // W2^T fp16 [768, 6144]
__device__ float g_as1[NNODES * H1N];
__device__ float g_ad1[NNODES * H1N];
__device__ float g_as2[NNODES * H2N];
__device__ float g_ad2[NNODES * H2N];
__device__ float g_alpha1[(size_t)NEDGES * H1N];
__device__ float g_alpha2[(size_t)NEDGES * H2N];
__device__ int   g_deg[NNODES];
__device__ int   g_cur[NNODES];
__device__ int   g_off[NNODES + 1];
__device__ int   g_eid[NEDGES];

// ---------------- helpers ----------------
__device__ __forceinline__ void cp16(unsigned dst, const void* src) {
    asm volatile("cp.async.cg.shared.global [%0], [%1], 16;" :: "r"(dst), "l"(src));
}
__device__ __forceinline__ uint32_t smem_u32(const void* p) {
    return (uint32_t)__cvta_generic_to_shared(p);
}

#define MMA_F16(d, a, b)                                                               \
    asm volatile(                                                                      \
        "mma.sync.aligned.m16n8k16.row.col.f32.f16.f16.f32 "                           \
        "{%0,%1,%2,%3},{%4,%5,%6,%7},{%8,%9},{%0,%1,%2,%3};"                           \
        : "+f"((d)[0]), "+f"((d)[1]), "+f"((d)[2]), "+f"((d)[3])                       \
        : "r"((a)[0]), "r"((a)[1]), "r"((a)[2]), "r"((a)[3]), "r"((b)[0]), "r"((b)[1]))

#define LDSM_X4(r, addr)                                                               \
    asm volatile("ldmatrix.sync.aligned.m8n8.x4.shared.b16 {%0,%1,%2,%3}, [%4];"       \
        : "=r"((r)[0]), "=r"((r)[1]), "=r"((r)[2]), "=r"((r)[3]) : "r"(addr))

// ---------------- fp32 -> fp16 convert ----------------
__global__ void f2h_kernel(const float* __restrict__ in, __half* __restrict__ out, int n4) {
    int i = blockIdx.x * blockDim.x + threadIdx.x;
    if (i < n4) {
        float4 v = ((const float4*)in)[i];
        __half2 h0 = __floats2half2_rn(v.x, v.y);
        __half2 h1 = __floats2half2_rn(v.z, v.w);
        uint2 u;
        u.x = *(uint32_t*)&h0; u.y = *(uint32_t*)&h1;
        ((uint2*)out)[i] = u;
    }
}

// ---------------- transpose + fp16 convert: in [R,C] fp32 -> out [C,R] fp16 ----------------
__global__ void transpose_h_kernel(const float* __restrict__ in, __half* __restrict__ out,
                                   int R, int C)
{
    __shared__ float t[32][33];
    int bx = blockIdx.x * 32, by = blockIdx.y * 32;
#pragma unroll
    for (int i = 0; i < 4; i++)
        t[threadIdx.y + 8 * i][threadIdx.x] =
            in[(size_t)(by + threadIdx.y + 8 * i) * C + bx + threadIdx.x];
    __syncthreads();
#pragma unroll
    for (int i = 0; i < 4; i++)
        out[(size_t)(bx + threadIdx.y + 8 * i) * R + by + threadIdx.x] =
            __float2half_rn(t[threadIdx.x][threadIdx.y + 8 * i]);
}

// ---------------- CSR build ----------------
__global__ void zero_counts_kernel() {
    int i = blockIdx.x * blockDim.x + threadIdx.x;
    if (i < NNODES) { g_deg[i] = 0; g_cur[i] = 0; }
}
__global__ void count_kernel(const int* __restrict__ dst) {
    int e = blockIdx.x * blockDim.x + threadIdx.x;
    if (e < NEDGES) atomicAdd(&g_deg[dst[e]], 1);
}
__global__ void scan_kernel() {
    __shared__ int s[1024];
    int t = threadIdx.x;
    int base = t * 8;
    int local[8];
    int run = 0;
#pragma unroll
    for (int i = 0; i < 8; i++) { local[i] = run; run += g_deg[base + i]; }
    s[t] = run;
    __syncthreads();
    for (int o = 1; o < 1024; o <<= 1) {
        int v = (t >= o) ? s[t - o] : 0;
        __syncthreads();
        s[t] += v;
        __syncthreads();
    }
    int prev = (t == 0) ? 0 : s[t - 1];
#pragma unroll
    for (int i = 0; i < 8; i++) g_off[base + i] = prev + local[i];
    if (t == 1023) g_off[NNODES] = s[1023];
}
__global__ void scatter_kernel(const int* __restrict__ dst) {
    int e = blockIdx.x * blockDim.x + threadIdx.x;
    if (e < NEDGES) {
        int d = dst[e];
        int p = atomicAdd(&g_cur[d], 1);
        g_eid[g_off[d] + p] = e;
    }
}

// ---------------- fp16 tensor-core GEMM ----------------
// C[M,N] = A[M,K] @ Bt^T ; A [M,K] half row-major, Bt [N,K] half row-major (K contig).
// Block 128x128, 4 warps (2x2), warp tile 64x64.
// K-tile 32, 3-stage cp.async pipeline, ldmatrix fragment loads.
// smem row stride 40 halves (80B): cp.async stores and LDSM both conflict-free.
#define HSTR 40
#define HG_STG  (2 * 128 * HSTR)           // halves per stage (A + B) = 10240
#define HG_SMEM (3 * HG_STG * 2)           // bytes = 61440

__global__ void __launch_bounds__(128, 2)
hgemm(const __half* __restrict__ A, const __half* __restrict__ Bt,
      float* __restrict__ C, int K, int N)
{
    extern __shared__ __half hs[];

    const int tid = threadIdx.x, wid = tid >> 5, lane = tid & 31;
    const int bn = blockIdx.x, bm = blockIdx.y;
    const int wm = (wid & 1) * 64;        // warp M origin
    const int wn = (wid >> 1) * 64;       // warp N origin
    const int g = lane >> 2, tg = lane & 3;

    const __half* Ag = A + (size_t)(bm * 128) * K;
    const __half* Bg = Bt + (size_t)(bn * 128) * K;

    float acc[32][4] = {};                // [mi*8 + ni][4]
    const int T = K / 32;

    auto load_tile = [&](int t) {
        int st = t % 3;
        __half* As = hs + st * HG_STG;
        __half* Bs = As + 128 * HSTR;
        int k0 = t * 32;
#pragma unroll
        for (int i = 0; i < 4; i++) {
            int ci = tid + i * 128;
            int r = ci >> 2, c = ci & 3;           // row 0..127, 16B-chunk 0..3
            cp16(smem_u32(&As[r * HSTR + c * 8]), Ag + (size_t)r * K + k0 + c * 8);
            cp16(smem_u32(&Bs[r * HSTR + c * 8]), Bg + (size_t)r * K + k0 + c * 8);
        }
        asm volatile("cp.async.commit_group;");
    };

    load_tile(0);
    if (T > 1) load_tile(1);

    // ldmatrix lane roles (identical mapping to the R8-verified kernel)
    const int a_r = lane & 15;
    const int a_k = (lane >> 4) * 8;
    const int b_r = ((lane >> 4) << 3) + (lane & 7);
    const int b_k = ((lane >> 3) & 1) * 8;

    for (int t = 0; t < T; t++) {
        asm volatile("cp.async.wait_group 1;");
        __syncthreads();
        if (t + 2 < T) load_tile(t + 2);

        const __half* Ab = hs + (t % 3) * HG_STG;
        const __half* Bb = Ab + 128 * HSTR;
#pragma unroll
        for (int kc = 0; kc < 2; kc++) {
            uint32_t a[4][4], b[8][2];
#pragma unroll
            for (int mi = 0; mi < 4; mi++) {
                uint32_t ad = smem_u32(&Ab[(wm + mi * 16 + a_r) * HSTR + kc * 16 + a_k]);
                LDSM_X4(a[mi], ad);
            }
#pragma unroll
            for (int p = 0; p < 4; p++) {
                uint32_t br[4];
                uint32_t bd = smem_u32(&Bb[(wn + p * 16 + b_r) * HSTR + kc * 16 + b_k]);
                LDSM_X4(br, bd);
                b[2 * p][0] = br[0]; b[2 * p][1] = br[1];
                b[2 * p + 1][0] = br[2]; b[2 * p + 1][1] = br[3];
            }
#pragma unroll
            for (int mi = 0; mi < 4; mi++)
#pragma unroll
                for (int ni = 0; ni < 8; ni++)
                    MMA_F16(acc[mi * 8 + ni], a[mi], b[ni]);
        }
        __syncthreads();
    }

    // epilogue
#pragma unroll
    for (int mi = 0; mi < 4; mi++) {
        int r0 = bm * 128 + wm + mi * 16 + g;
#pragma unroll
        for (int ni = 0; ni < 8; ni++) {
            int c = bn * 128 + wn + ni * 8 + tg * 2;
            float* p = C + (size_t)r0 * N + c;
            *(float2*)p = make_float2(acc[mi * 8 + ni][0], acc[mi * 8 + ni][1]);
            *(float2*)(p + (size_t)8 * N) = make_float2(acc[mi * 8 + ni][2], acc[mi * 8 + ni][3]);
        }
    }
}

// ---------------- per-(node,head) attention coefficients ----------------
__global__ void alphas_kernel(const float* __restrict__ h,
                              const float* __restrict__ a_s, const float* __restrict__ a_d,
                              float* __restrict__ out_s, float* __restrict__ out_d,
                              int H, int C)
{
    int w = (blockIdx.x * blockDim.x + threadIdx.x) >> 5;
    int lane = threadIdx.x & 31;
    if (w >= NNODES * H) return;
    int n = w / H, hd = w % H;
    const float* hp  = h + (size_t)n * H * C + (size_t)hd * C;
    const float* asp = a_s + (size_t)hd * C;
    const float* adp = a_d + (size_t)hd * C;
    float ss = 0.f, sd = 0.f;
    for (int c = lane; c < C; c += 32) {
        float v = hp[c];
        ss += v * asp[c];
        sd += v * adp[c];
    }
#pragma unroll
    for (int o = 16; o; o >>= 1) {
        ss += __shfl_down_sync(0xffffffffu, ss, o);
        sd += __shfl_down_sync(0xffffffffu, sd, o);
    }
    if (lane == 0) { out_s[w] = ss; out_d[w] = sd; }
}

// ---------------- per-(dst,head) segment softmax ----------------
__global__ void softmax_kernel(const int* __restrict__ src,
                               const float* __restrict__ as, const float* __restrict__ ad,
                               float* __restrict__ alpha, int H)
{
    int idx = blockIdx.x * blockDim.x + threadIdx.x;
    if (idx >= NNODES * H) return;
    int d = idx / H, hd = idx % H;
    int s0 = g_off[d], s1 = g_off[d + 1];
    if (s0 == s1) return;
    float adv = ad[idx];

    float m = -1e30f;
    for (int i = s0; i < s1; i++) {
        int e = g_eid[i];
        float x = as[src[e] * H + hd] + adv;
        x = (x > 0.f) ? x : NEG_SLOPE * x;
        m = fmaxf(m, x);
    }
    float sum = 0.f;
    for (int i = s0; i < s1; i++) {
        int e = g_eid[i];
        float x = as[src[e] * H + hd] + adv;
        x = (x > 0.f) ? x : NEG_SLOPE * x;
        float w = __expf(x - m);
        alpha[(size_t)e * H + hd] = w;
        sum += w;
    }
    float inv = 1.f / (sum + EPSV);
    for (int i = s0; i < s1; i++) {
        int e = g_eid[i];
        alpha[(size_t)e * H + hd] *= inv;
    }
}

// ---------------- aggregation ----------------
// acc = sum_e alpha * h[src] + b; layer1 (do_elu): out_h = fp16(elu(acc)); layer2: out_f = acc.
// Block order is HEAD-MAJOR (d = bid % N, hd = bid / N) so concurrently-resident blocks
// gather from ONE head's 24MB slice of h -> L2-resident working set.
__global__ void __launch_bounds__(192)
aggregate_kernel(const int* __restrict__ src, const float* __restrict__ alpha,
                 const float* __restrict__ h, float* __restrict__ out_f,
                 __half* __restrict__ out_h, const float* __restrict__ bias,
                 int H, int C, int do_elu)
{
    int d  = blockIdx.x % NNODES;
    int hd = blockIdx.x / NNODES;
    int t  = threadIdx.x;
    int s0 = g_off[d], s1 = g_off[d + 1];
    size_t rs = (size_t)H * C;

    float4 acc = make_float4(0.f, 0.f, 0.f, 0.f);
    for (int i = s0; i < s1; i++) {
        int e = g_eid[i];
        float a = alpha[(size_t)e * H + hd];
        float4 v = *(((const float4*)(h + (size_t)src[e] * rs + (size_t)hd * C)) + t);
        acc.x += a * v.x; acc.y += a * v.y; acc.z += a * v.z; acc.w += a * v.w;
    }
    float4 b = *(((const float4*)(bias + (size_t)hd * C)) + t);
    acc.x += b.x; acc.y += b.y; acc.z += b.z; acc.w += b.w;
    if (do_elu) {
        acc.x = (acc.x > 0.f) ? acc.x : expm1f(acc.x);
        acc.y = (acc.y > 0.f) ? acc.y : expm1f(acc.y);
        acc.z = (acc.z > 0.f) ? acc.z : expm1f(acc.z);
        acc.w = (acc.w > 0.f) ? acc.w : expm1f(acc.w);
        __half2 h0 = __floats2half2_rn(acc.x, acc.y);
        __half2 h1 = __floats2half2_rn(acc.z, acc.w);
        uint2 u; u.x = *(uint32_t*)&h0; u.y = *(uint32_t*)&h1;
        *(((uint2*)(out_h + (size_t)d * rs + (size_t)hd * C)) + t) = u;
    } else {
        *(((float4*)(out_f + (size_t)d * rs + (size_t)hd * C)) + t) = acc;
    }
}

// ---------------- launch ----------------
extern "C" void kernel_launch(void* const* d_in, const int* in_sizes, int n_in,
                              void* d_out, int out_size)
{
    const float* x    = (const float*)d_in[0];
    const float* W1   = (const float*)d_in[1];
    const float* a_s1 = (const float*)d_in[2];
    const float* a_d1 = (const float*)d_in[3];
    const float* b1   = (const float*)d_in[4];
    const float* W2   = (const float*)d_in[5];
    const float* a_s2 = (const float*)d_in[6];
    const float* a_d2 = (const float*)d_in[7];
    const float* b2   = (const float*)d_in[8];
    const int* edges  = (const int*)d_in[9];
    const int* src = edges;
    const int* dst = edges + NEDGES;
    float* out = (float*)d_out;

    float *h1, *h2, *as1, *ad1, *as2, *ad2, *al1, *al2;
    __half *xh, *o1h, *w1th, *w2th;
    cudaGetSymbolAddress((void**)&h1,   g_h1);
    cudaGetSymbolAddress((void**)&h2,   g_h2);
    cudaGetSymbolAddress((void**)&xh,   g_xh);
    cudaGetSymbolAddress((void**)&o1h,  g_o1h);
    cudaGetSymbolAddress((void**)&w1th, g_w1th);
    cudaGetSymbolAddress((void**)&w2th, g_w2th);
    cudaGetSymbolAddress((void**)&as1,  g_as1);
    cudaGetSymbolAddress((void**)&ad1,  g_ad1);
    cudaGetSymbolAddress((void**)&as2,  g_as2);
    cudaGetSymbolAddress((void**)&ad2,  g_ad2);
    cudaGetSymbolAddress((void**)&al1,  g_alpha1);
    cudaGetSymbolAddress((void**)&al2,  g_alpha2);

    cudaFuncSetAttribute(hgemm, cudaFuncAttributeMaxDynamicSharedMemorySize, HG_SMEM);

    dim3 tblk(32, 8);

    // 0: x -> fp16
    f2h_kernel<<<(NNODES * DIN / 4 + 255) / 256, 256>>>(x, xh, NNODES * DIN / 4);
    // 1: W1 [768,6144] -> W1^T fp16 [6144,768]
    {
        dim3 gt((H1N * DHID) / 32, DIN / 32);
        transpose_h_kernel<<<gt, tblk>>>(W1, w1th, DIN, H1N * DHID);
    }
    // 2: W2 [6144,768] -> W2^T fp16 [768,6144]
    {
        dim3 gt(DHID / 32, (H1N * DHID) / 32);
        transpose_h_kernel<<<gt, tblk>>>(W2, w2th, H1N * DHID, DHID);
    }
    // 3: GEMM1 (ncu capture slot)  h1 = x @ W1  [8192, 6144]
    {
        dim3 grid((H1N * DHID) / 128, NNODES / 128);   // (48, 64)
        hgemm<<<grid, 128, HG_SMEM>>>(xh, w1th, h1, DIN, H1N * DHID);
    }
    // CSR build
    zero_counts_kernel<<<(NNODES + 255) / 256, 256>>>();
    count_kernel<<<(NEDGES + 255) / 256, 256>>>(dst);
    scan_kernel<<<1, 1024>>>();
    scatter_kernel<<<(NEDGES + 255) / 256, 256>>>(dst);
    // layer-1 attention + aggregation (writes o1 as fp16)
    alphas_kernel<<<(NNODES * H1N * 32 + 255) / 256, 256>>>(h1, a_s1, a_d1, as1, ad1, H1N, DHID);
    softmax_kernel<<<(NNODES * H1N + 255) / 256, 256>>>(src, as1, ad1, al1, H1N);
    aggregate_kernel<<<NNODES * H1N, DHID / 4>>>(src, al1, h1, nullptr, o1h, b1, H1N, DHID, 1);
    // GEMM2  h2 = o1 @ W2  [8192, 768]
    {
        dim3 grid((H2N * DHID) / 128, NNODES / 128);   // (6, 64)
        hgemm<<<grid, 128, HG_SMEM>>>(o1h, w2th, h2, H1N * DHID, H2N * DHID);
    }
    // layer-2 attention + aggregation (fp32 out)
    alphas_kernel<<<(NNODES * H2N * 32 + 255) / 256, 256>>>(h2, a_s2, a_d2, as2, ad2, H2N, DHID);
    softmax_kernel<<<(NNODES * H2N + 255) / 256, 256>>>(src, as2, ad2, al2, H2N);
    aggregate_kernel<<<NNODES * H2N, DHID / 4>>>(src, al2, h2, out, nullptr, b2, H2N, DHID, 0);
}

// round 10
// speedup vs baseline: 1.4058x; 1.0805x over previous
#include <cuda_runtime.h>
#include <cuda_fp16.h>
#include <math.h>
#include <cstdint>

// ---------------- problem constants ----------------
#define NNODES 8192
#define NEDGES 65536
#define DIN    768
#define DHID   768
#define H1N    8
#define H2N    1
#define NEG_SLOPE 0.2f
#define EPSV 1e-16f
#define SPLITK 3
#define K2CHUNK ((H1N * DHID) / SPLITK)     // 2048

// ---------------- scratch (device globals; no allocs allowed) ----------------
__device__ __half g_h1h[(size_t)NNODES * (H1N * DHID)];    // x @ W1 fp16 [8192, 6144]
__device__ float  g_part[(size_t)SPLITK * NNODES * DHID];  // GEMM2 split-K partials
__device__ float  g_h2[(size_t)NNODES * DHID];             // o1 @ W2 summed [8192, 768]
__device__ __half g_xh [(size_t)NNODES * DIN];             // x fp16
__device__ __half g_o1h[(size_t)NNODES * (H1N * DHID)];    // elu(agg1+b1) fp16 (GEMM2 A)
__device__ __half g_w1th[(size_t)(H1N * DHID) * DIN];      // W1^T fp16 [6144, 768]
__device__ __half g_w2th[(size_t)DHID * (H1N * DHID)];     // W2^T fp16 [768, 6144]
__device__ float g_as1[NNODES * H1N];
__device__ float g_ad1[NNODES * H1N];
__device__ float g_as2[NNODES];
__device__ float g_ad2[NNODES];
__device__ float g_alpha1[(size_t)NEDGES * H1N];
__device__ float g_alpha2[(size_t)NEDGES];
__device__ int   g_deg[NNODES];
__device__ int   g_cur[NNODES];
__device__ int   g_off[NNODES + 1];
__device__ int   g_eid[NEDGES];

// ---------------- helpers ----------------
__device__ __forceinline__ void cp16(unsigned dst, const void* src) {
    asm volatile("cp.async.cg.shared.global [%0], [%1], 16;" :: "r"(dst), "l"(src));
}
__device__ __forceinline__ uint32_t smem_u32(const void* p) {
    return (uint32_t)__cvta_generic_to_shared(p);
}

#define MMA_F16(d, a, b)                                                               \
    asm volatile(                                                                      \
        "mma.sync.aligned.m16n8k16.row.col.f32.f16.f16.f32 "                           \
        "{%0,%1,%2,%3},{%4,%5,%6,%7},{%8,%9},{%0,%1,%2,%3};"                           \
        : "+f"((d)[0]), "+f"((d)[1]), "+f"((d)[2]), "+f"((d)[3])                       \
        : "r"((a)[0]), "r"((a)[1]), "r"((a)[2]), "r"((a)[3]), "r"((b)[0]), "r"((b)[1]))

#define LDSM_X4(r, addr)                                                               \
    asm volatile("ldmatrix.sync.aligned.m8n8.x4.shared.b16 {%0,%1,%2,%3}, [%4];"       \
        : "=r"((r)[0]), "=r"((r)[1]), "=r"((r)[2]), "=r"((r)[3]) : "r"(addr))

// ---------------- fp32 -> fp16 convert ----------------
__global__ void f2h_kernel(const float* __restrict__ in, __half* __restrict__ out, int n4) {
    int i = blockIdx.x * blockDim.x + threadIdx.x;
    if (i < n4) {
        float4 v = ((const float4*)in)[i];
        __half2 h0 = __floats2half2_rn(v.x, v.y);
        __half2 h1 = __floats2half2_rn(v.z, v.w);
        uint2 u;
        u.x = *(uint32_t*)&h0; u.y = *(uint32_t*)&h1;
        ((uint2*)out)[i] = u;
    }
}

// ---------------- transpose + fp16 convert: in [R,C] fp32 -> out [C,R] fp16 ----------------
__global__ void transpose_h_kernel(const float* __restrict__ in, __half* __restrict__ out,
                                   int R, int C)
{
    __shared__ float t[32][33];
    int bx = blockIdx.x * 32, by = blockIdx.y * 32;
#pragma unroll
    for (int i = 0; i < 4; i++)
        t[threadIdx.y + 8 * i][threadIdx.x] =
            in[(size_t)(by + threadIdx.y + 8 * i) * C + bx + threadIdx.x];
    __syncthreads();
#pragma unroll
    for (int i = 0; i < 4; i++)
        out[(size_t)(bx + threadIdx.y + 8 * i) * R + by + threadIdx.x] =
            __float2half_rn(t[threadIdx.x][threadIdx.y + 8 * i]);
}

// ---------------- CSR build ----------------
__global__ void zero_counts_kernel() {
    int i = blockIdx.x * blockDim.x + threadIdx.x;
    if (i < NNODES) { g_deg[i] = 0; g_cur[i] = 0; }
}
__global__ void count_kernel(const int* __restrict__ dst) {
    int e = blockIdx.x * blockDim.x + threadIdx.x;
    if (e < NEDGES) atomicAdd(&g_deg[dst[e]], 1);
}
__global__ void scan_kernel() {
    __shared__ int s[1024];
    int t = threadIdx.x;
    int base = t * 8;
    int local[8];
    int run = 0;
#pragma unroll
    for (int i = 0; i < 8; i++) { local[i] = run; run += g_deg[base + i]; }
    s[t] = run;
    __syncthreads();
    for (int o = 1; o < 1024; o <<= 1) {
        int v = (t >= o) ? s[t - o] : 0;
        __syncthreads();
        s[t] += v;
        __syncthreads();
    }
    int prev = (t == 0) ? 0 : s[t - 1];
#pragma unroll
    for (int i = 0; i < 8; i++) g_off[base + i] = prev + local[i];
    if (t == 1023) g_off[NNODES] = s[1023];
}
__global__ void scatter_kernel(const int* __restrict__ dst) {
    int e = blockIdx.x * blockDim.x + threadIdx.x;
    if (e < NEDGES) {
        int d = dst[e];
        int p = atomicAdd(&g_cur[d], 1);
        g_eid[g_off[d] + p] = e;
    }
}

// ---------------- fp16 tensor-core GEMM ----------------
// C[M,N] tile = A[M, k0:k0+kLen] @ Bt[k0:k0+kLen]^T.  A, Bt row-major with row stride lda.
// Block 128x128, 4 warps (2x2), warp tile 64x64, K-tile 32, 3-stage cp.async, ldmatrix.
// Output: fp16 to Ch if non-null, else fp32 to Cf (Cf offset by blockIdx.z partial buffer).
#define HSTR 40
#define HG_STG  (2 * 128 * HSTR)           // halves per stage (A + B) = 10240
#define HG_SMEM (3 * HG_STG * 2)           // bytes = 61440

__global__ void __launch_bounds__(128, 2)
hgemm(const __half* __restrict__ A, const __half* __restrict__ Bt,
      float* __restrict__ Cf, __half* __restrict__ Ch,
      int lda, int kLen, int N)
{
    extern __shared__ __half hs[];

    const int tid = threadIdx.x, wid = tid >> 5, lane = tid & 31;
    const int bn = blockIdx.x, bm = blockIdx.y, bz = blockIdx.z;
    const int k0 = bz * kLen;
    const int wm = (wid & 1) * 64;
    const int wn = (wid >> 1) * 64;
    const int g = lane >> 2, tg = lane & 3;

    const __half* Ag = A + (size_t)(bm * 128) * lda + k0;
    const __half* Bg = Bt + (size_t)(bn * 128) * lda + k0;

    float acc[32][4] = {};
    const int T = kLen / 32;

    auto load_tile = [&](int t) {
        int st = t % 3;
        __half* As = hs + st * HG_STG;
        __half* Bs = As + 128 * HSTR;
        int kk = t * 32;
#pragma unroll
        for (int i = 0; i < 4; i++) {
            int ci = tid + i * 128;
            int r = ci >> 2, c = ci & 3;
            cp16(smem_u32(&As[r * HSTR + c * 8]), Ag + (size_t)r * lda + kk + c * 8);
            cp16(smem_u32(&Bs[r * HSTR + c * 8]), Bg + (size_t)r * lda + kk + c * 8);
        }
        asm volatile("cp.async.commit_group;");
    };

    load_tile(0);
    if (T > 1) load_tile(1);

    const int a_r = lane & 15;
    const int a_k = (lane >> 4) * 8;
    const int b_r = ((lane >> 4) << 3) + (lane & 7);
    const int b_k = ((lane >> 3) & 1) * 8;

    for (int t = 0; t < T; t++) {
        asm volatile("cp.async.wait_group 1;");
        __syncthreads();
        if (t + 2 < T) load_tile(t + 2);

        const __half* Ab = hs + (t % 3) * HG_STG;
        const __half* Bb = Ab + 128 * HSTR;
#pragma unroll
        for (int kc = 0; kc < 2; kc++) {
            uint32_t a[4][4], b[8][2];
#pragma unroll
            for (int mi = 0; mi < 4; mi++) {
                uint32_t ad = smem_u32(&Ab[(wm + mi * 16 + a_r) * HSTR + kc * 16 + a_k]);
                LDSM_X4(a[mi], ad);
            }
#pragma unroll
            for (int p = 0; p < 4; p++) {
                uint32_t br[4];
                uint32_t bd = smem_u32(&Bb[(wn + p * 16 + b_r) * HSTR + kc * 16 + b_k]);
                LDSM_X4(br, bd);
                b[2 * p][0] = br[0]; b[2 * p][1] = br[1];
                b[2 * p + 1][0] = br[2]; b[2 * p + 1][1] = br[3];
            }
#pragma unroll
            for (int mi = 0; mi < 4; mi++)
#pragma unroll
                for (int ni = 0; ni < 8; ni++)
                    MMA_F16(acc[mi * 8 + ni], a[mi], b[ni]);
        }
        __syncthreads();
    }

    // epilogue
    if (Ch) {
#pragma unroll
        for (int mi = 0; mi < 4; mi++) {
            int r0 = bm * 128 + wm + mi * 16 + g;
#pragma unroll
            for (int ni = 0; ni < 8; ni++) {
                int c = bn * 128 + wn + ni * 8 + tg * 2;
                __half* p = Ch + (size_t)r0 * N + c;
                __half2 v0 = __floats2half2_rn(acc[mi * 8 + ni][0], acc[mi * 8 + ni][1]);
                __half2 v1 = __floats2half2_rn(acc[mi * 8 + ni][2], acc[mi * 8 + ni][3]);
                *(__half2*)p = v0;
                *(__half2*)(p + (size_t)8 * N) = v1;
            }
        }
    } else {
        float* Cp = Cf + (size_t)bz * NNODES * DHID;
#pragma unroll
        for (int mi = 0; mi < 4; mi++) {
            int r0 = bm * 128 + wm + mi * 16 + g;
#pragma unroll
            for (int ni = 0; ni < 8; ni++) {
                int c = bn * 128 + wn + ni * 8 + tg * 2;
                float* p = Cp + (size_t)r0 * N + c;
                *(float2*)p = make_float2(acc[mi * 8 + ni][0], acc[mi * 8 + ni][1]);
                *(float2*)(p + (size_t)8 * N) = make_float2(acc[mi * 8 + ni][2], acc[mi * 8 + ni][3]);
            }
        }
    }
}

// ---------------- per-(node,head) attention coefficients (fp16 h) ----------------
__global__ void alphas_h_kernel(const __half* __restrict__ h,
                                const float* __restrict__ a_s, const float* __restrict__ a_d,
                                float* __restrict__ out_s, float* __restrict__ out_d,
                                int H, int C)
{
    int w = (blockIdx.x * blockDim.x + threadIdx.x) >> 5;
    int lane = threadIdx.x & 31;
    if (w >= NNODES * H) return;
    int n = w / H, hd = w % H;
    const __half* hp = h + (size_t)n * H * C + (size_t)hd * C;
    const float* asp = a_s + (size_t)hd * C;
    const float* adp = a_d + (size_t)hd * C;
    float ss = 0.f, sd = 0.f;
    for (int c = lane; c < C; c += 32) {
        float v = __half2float(hp[c]);
        ss += v * asp[c];
        sd += v * adp[c];
    }
#pragma unroll
    for (int o = 16; o; o >>= 1) {
        ss += __shfl_down_sync(0xffffffffu, ss, o);
        sd += __shfl_down_sync(0xffffffffu, sd, o);
    }
    if (lane == 0) { out_s[w] = ss; out_d[w] = sd; }
}

// ---------------- split-K reduce + layer-2 alphas (fused) ----------------
// warp per node: h2[n,:] = sum_p part[p][n,:]; as2/ad2 = dot(h2[n,:], a_s2/a_d2)
__global__ void reduce_alphas2_kernel(const float* __restrict__ part,
                                      float* __restrict__ h2,
                                      const float* __restrict__ a_s, const float* __restrict__ a_d,
                                      float* __restrict__ out_s, float* __restrict__ out_d)
{
    int w = (blockIdx.x * blockDim.x + threadIdx.x) >> 5;
    int lane = threadIdx.x & 31;
    if (w >= NNODES) return;
    const size_t base = (size_t)w * DHID;
    const size_t pstride = (size_t)NNODES * DHID;
    float ss = 0.f, sd = 0.f;
    for (int c = lane; c < DHID; c += 32) {
        float s = part[base + c] + part[pstride + base + c] + part[2 * pstride + base + c];
        h2[base + c] = s;
        ss += s * a_s[c];
        sd += s * a_d[c];
    }
#pragma unroll
    for (int o = 16; o; o >>= 1) {
        ss += __shfl_down_sync(0xffffffffu, ss, o);
        sd += __shfl_down_sync(0xffffffffu, sd, o);
    }
    if (lane == 0) { out_s[w] = ss; out_d[w] = sd; }
}

// ---------------- per-(dst,head) segment softmax ----------------
__global__ void softmax_kernel(const int* __restrict__ src,
                               const float* __restrict__ as, const float* __restrict__ ad,
                               float* __restrict__ alpha, int H)
{
    int idx = blockIdx.x * blockDim.x + threadIdx.x;
    if (idx >= NNODES * H) return;
    int d = idx / H, hd = idx % H;
    int s0 = g_off[d], s1 = g_off[d + 1];
    if (s0 == s1) return;
    float adv = ad[idx];

    float m = -1e30f;
    for (int i = s0; i < s1; i++) {
        int e = g_eid[i];
        float x = as[src[e] * H + hd] + adv;
        x = (x > 0.f) ? x : NEG_SLOPE * x;
        m = fmaxf(m, x);
    }
    float sum = 0.f;
    for (int i = s0; i < s1; i++) {
        int e = g_eid[i];
        float x = as[src[e] * H + hd] + adv;
        x = (x > 0.f) ? x : NEG_SLOPE * x;
        float w = __expf(x - m);
        alpha[(size_t)e * H + hd] = w;
        sum += w;
    }
    float inv = 1.f / (sum + EPSV);
    for (int i = s0; i < s1; i++) {
        int e = g_eid[i];
        alpha[(size_t)e * H + hd] *= inv;
    }
}

// ---------------- layer-1 aggregation: fp16 gather, fp16 out ----------------
// HEAD-MAJOR block order: concurrently resident blocks share one head's h slice in L2.
__global__ void __launch_bounds__(192)
aggregate1_kernel(const int* __restrict__ src, const float* __restrict__ alpha,
                  const __half* __restrict__ h, __half* __restrict__ out_h,
                  const float* __restrict__ bias)
{
    int d  = blockIdx.x % NNODES;
    int hd = blockIdx.x / NNODES;
    int t  = threadIdx.x;
    int s0 = g_off[d], s1 = g_off[d + 1];
    const size_t rs = (size_t)H1N * DHID;

    float4 acc = make_float4(0.f, 0.f, 0.f, 0.f);
    for (int i = s0; i < s1; i++) {
        int e = g_eid[i];
        float a = alpha[(size_t)e * H1N + hd];
        uint2 u = *(((const uint2*)(h + (size_t)src[e] * rs + (size_t)hd * DHID)) + t);
        __half2 v0 = *(__half2*)&u.x;
        __half2 v1 = *(__half2*)&u.y;
        float2 f0 = __half22float2(v0);
        float2 f1 = __half22float2(v1);
        acc.x += a * f0.x; acc.y += a * f0.y; acc.z += a * f1.x; acc.w += a * f1.y;
    }
    float4 b = *(((const float4*)(bias + (size_t)hd * DHID)) + t);
    acc.x += b.x; acc.y += b.y; acc.z += b.z; acc.w += b.w;
    acc.x = (acc.x > 0.f) ? acc.x : expm1f(acc.x);
    acc.y = (acc.y > 0.f) ? acc.y : expm1f(acc.y);
    acc.z = (acc.z > 0.f) ? acc.z : expm1f(acc.z);
    acc.w = (acc.w > 0.f) ? acc.w : expm1f(acc.w);
    __half2 h0 = __floats2half2_rn(acc.x, acc.y);
    __half2 h1 = __floats2half2_rn(acc.z, acc.w);
    uint2 u; u.x = *(uint32_t*)&h0; u.y = *(uint32_t*)&h1;
    *(((uint2*)(out_h + (size_t)d * rs + (size_t)hd * DHID)) + t) = u;
}

// ---------------- layer-2 aggregation: fp32 gather, fp32 out ----------------
__global__ void __launch_bounds__(192)
aggregate2_kernel(const int* __restrict__ src, const float* __restrict__ alpha,
                  const float* __restrict__ h, float* __restrict__ out,
                  const float* __restrict__ bias)
{
    int d = blockIdx.x;
    int t = threadIdx.x;
    int s0 = g_off[d], s1 = g_off[d + 1];

    float4 acc = make_float4(0.f, 0.f, 0.f, 0.f);
    for (int i = s0; i < s1; i++) {
        int e = g_eid[i];
        float a = alpha[e];
        float4 v = *(((const float4*)(h + (size_t)src[e] * DHID)) + t);
        acc.x += a * v.x; acc.y += a * v.y; acc.z += a * v.z; acc.w += a * v.w;
    }
    float4 b = *(((const float4*)bias) + t);
    acc.x += b.x; acc.y += b.y; acc.z += b.z; acc.w += b.w;
    *(((float4*)(out + (size_t)d * DHID)) + t) = acc;
}

// ---------------- launch ----------------
extern "C" void kernel_launch(void* const* d_in, const int* in_sizes, int n_in,
                              void* d_out, int out_size)
{
    const float* x    = (const float*)d_in[0];
    const float* W1   = (const float*)d_in[1];
    const float* a_s1 = (const float*)d_in[2];
    const float* a_d1 = (const float*)d_in[3];
    const float* b1   = (const float*)d_in[4];
    const float* W2   = (const float*)d_in[5];
    const float* a_s2 = (const float*)d_in[6];
    const float* a_d2 = (const float*)d_in[7];
    const float* b2   = (const float*)d_in[8];
    const int* edges  = (const int*)d_in[9];
    const int* src = edges;
    const int* dst = edges + NEDGES;
    float* out = (float*)d_out;

    float *part, *h2, *as1, *ad1, *as2, *ad2, *al1, *al2;
    __half *h1h, *xh, *o1h, *w1th, *w2th;
    cudaGetSymbolAddress((void**)&h1h,  g_h1h);
    cudaGetSymbolAddress((void**)&part, g_part);
    cudaGetSymbolAddress((void**)&h2,   g_h2);
    cudaGetSymbolAddress((void**)&xh,   g_xh);
    cudaGetSymbolAddress((void**)&o1h,  g_o1h);
    cudaGetSymbolAddress((void**)&w1th, g_w1th);
    cudaGetSymbolAddress((void**)&w2th, g_w2th);
    cudaGetSymbolAddress((void**)&as1,  g_as1);
    cudaGetSymbolAddress((void**)&ad1,  g_ad1);
    cudaGetSymbolAddress((void**)&as2,  g_as2);
    cudaGetSymbolAddress((void**)&ad2,  g_ad2);
    cudaGetSymbolAddress((void**)&al1,  g_alpha1);
    cudaGetSymbolAddress((void**)&al2,  g_alpha2);

    cudaFuncSetAttribute(hgemm, cudaFuncAttributeMaxDynamicSharedMemorySize, HG_SMEM);

    dim3 tblk(32, 8);

    // 0: x -> fp16
    f2h_kernel<<<(NNODES * DIN / 4 + 255) / 256, 256>>>(x, xh, NNODES * DIN / 4);
    // 1: W1 [768,6144] -> W1^T fp16 [6144,768]
    {
        dim3 gt((H1N * DHID) / 32, DIN / 32);
        transpose_h_kernel<<<gt, tblk>>>(W1, w1th, DIN, H1N * DHID);
    }
    // 2: W2 [6144,768] -> W2^T fp16 [768,6144]
    {
        dim3 gt(DHID / 32, (H1N * DHID) / 32);
        transpose_h_kernel<<<gt, tblk>>>(W2, w2th, H1N * DHID, DHID);
    }
    // 3: GEMM1 (ncu capture slot)  h1h = fp16(x @ W1)  [8192, 6144]
    {
        dim3 grid((H1N * DHID) / 128, NNODES / 128, 1);   // (48, 64)
        hgemm<<<grid, 128, HG_SMEM>>>(xh, w1th, nullptr, h1h, DIN, DIN, H1N * DHID);
    }
    // CSR build
    zero_counts_kernel<<<(NNODES + 255) / 256, 256>>>();
    count_kernel<<<(NEDGES + 255) / 256, 256>>>(dst);
    scan_kernel<<<1, 1024>>>();
    scatter_kernel<<<(NEDGES + 255) / 256, 256>>>(dst);
    // layer-1 attention + aggregation (fp16 h1, fp16 o1)
    alphas_h_kernel<<<(NNODES * H1N * 32 + 255) / 256, 256>>>(h1h, a_s1, a_d1, as1, ad1, H1N, DHID);
    softmax_kernel<<<(NNODES * H1N + 255) / 256, 256>>>(src, as1, ad1, al1, H1N);
    aggregate1_kernel<<<NNODES * H1N, DHID / 4>>>(src, al1, h1h, o1h, b1);
    // GEMM2  split-K 3: part[p] = o1[:, p*2048:(p+1)*2048] @ W2[p-chunk]  [8192, 768] each
    {
        dim3 grid((H2N * DHID) / 128, NNODES / 128, SPLITK);   // (6, 64, 3)
        hgemm<<<grid, 128, HG_SMEM>>>(o1h, w2th, part, nullptr, H1N * DHID, K2CHUNK, H2N * DHID);
    }
    // split-K reduce + layer-2 alphas (fused)
    reduce_alphas2_kernel<<<(NNODES * 32 + 255) / 256, 256>>>(part, h2, a_s2, a_d2, as2, ad2);
    softmax_kernel<<<(NNODES + 255) / 256, 256>>>(src, as2, ad2, al2, H2N);
    aggregate2_kernel<<<NNODES, DHID / 4>>>(src, al2, h2, out, b2);
}

// round 11
// speedup vs baseline: 1.5748x; 1.1202x over previous
#include <cuda_runtime.h>
#include <cuda_fp16.h>
#include <math.h>
#include <cstdint>

// ---------------- problem constants ----------------
#define NNODES 8192
#define NEDGES 65536
#define DIN    768
#define DHID   768
#define H1N    8
#define H2N    1
#define NEG_SLOPE 0.2f
#define EPSV 1e-16f
#define SPLITK 3
#define K2CHUNK ((H1N * DHID) / SPLITK)     // 2048

// ---------------- scratch (device globals; no allocs allowed) ----------------
__device__ __half g_h1h[(size_t)NNODES * (H1N * DHID)];    // x @ W1 fp16 [8192, 6144]
__device__ float  g_part[(size_t)SPLITK * NNODES * DHID];  // GEMM2 split-K partials
__device__ float  g_h2[(size_t)NNODES * DHID];             // o1 @ W2 summed [8192, 768]
__device__ __half g_xh [(size_t)NNODES * DIN];             // x fp16
__device__ __half g_o1h[(size_t)NNODES * (H1N * DHID)];    // elu(agg1+b1) fp16 (GEMM2 A)
__device__ __half g_w1th[(size_t)(H1N * DHID) * DIN];      // W1^T fp16 [6144, 768]
__device__ __half g_w2th[(size_t)DHID * (H1N * DHID)];     // W2^T fp16 [768, 6144]
__device__ float g_as1[NNODES * H1N];
__device__ float g_ad1[NNODES * H1N];
__device__ float g_as2[NNODES];
__device__ float g_ad2[NNODES];
__device__ float g_alpha1[(size_t)NEDGES * H1N];
__device__ float g_alpha2[(size_t)NEDGES];
__device__ int   g_deg[NNODES];
__device__ int   g_cur[NNODES];
__device__ int   g_off[NNODES + 1];
__device__ int   g_eid[NEDGES];

// ---------------- helpers ----------------
__device__ __forceinline__ void cp16(unsigned dst, const void* src) {
    asm volatile("cp.async.cg.shared.global [%0], [%1], 16;" :: "r"(dst), "l"(src));
}
__device__ __forceinline__ uint32_t smem_u32(const void* p) {
    return (uint32_t)__cvta_generic_to_shared(p);
}

#define MMA_F16(d, a, b)                                                               \
    asm volatile(                                                                      \
        "mma.sync.aligned.m16n8k16.row.col.f32.f16.f16.f32 "                           \
        "{%0,%1,%2,%3},{%4,%5,%6,%7},{%8,%9},{%0,%1,%2,%3};"                           \
        : "+f"((d)[0]), "+f"((d)[1]), "+f"((d)[2]), "+f"((d)[3])                       \
        : "r"((a)[0]), "r"((a)[1]), "r"((a)[2]), "r"((a)[3]), "r"((b)[0]), "r"((b)[1]))

#define LDSM_X4(r, addr)                                                               \
    asm volatile("ldmatrix.sync.aligned.m8n8.x4.shared.b16 {%0,%1,%2,%3}, [%4];"       \
        : "=r"((r)[0]), "=r"((r)[1]), "=r"((r)[2]), "=r"((r)[3]) : "r"(addr))

// ---------------- fp32 -> fp16 convert ----------------
__global__ void f2h_kernel(const float* __restrict__ in, __half* __restrict__ out, int n4) {
    int i = blockIdx.x * blockDim.x + threadIdx.x;
    if (i < n4) {
        float4 v = ((const float4*)in)[i];
        __half2 h0 = __floats2half2_rn(v.x, v.y);
        __half2 h1 = __floats2half2_rn(v.z, v.w);
        uint2 u;
        u.x = *(uint32_t*)&h0; u.y = *(uint32_t*)&h1;
        ((uint2*)out)[i] = u;
    }
}

// ---------------- transpose + fp16 convert: in [R,C] fp32 -> out [C,R] fp16 ----------------
__global__ void transpose_h_kernel(const float* __restrict__ in, __half* __restrict__ out,
                                   int R, int C)
{
    __shared__ float t[32][33];
    int bx = blockIdx.x * 32, by = blockIdx.y * 32;
#pragma unroll
    for (int i = 0; i < 4; i++)
        t[threadIdx.y + 8 * i][threadIdx.x] =
            in[(size_t)(by + threadIdx.y + 8 * i) * C + bx + threadIdx.x];
    __syncthreads();
#pragma unroll
    for (int i = 0; i < 4; i++)
        out[(size_t)(bx + threadIdx.y + 8 * i) * R + by + threadIdx.x] =
            __float2half_rn(t[threadIdx.x][threadIdx.y + 8 * i]);
}

// ---------------- CSR build ----------------
__global__ void zero_counts_kernel() {
    int i = blockIdx.x * blockDim.x + threadIdx.x;
    if (i < NNODES) { g_deg[i] = 0; g_cur[i] = 0; }
}
__global__ void count_kernel(const int* __restrict__ dst) {
    int e = blockIdx.x * blockDim.x + threadIdx.x;
    if (e < NEDGES) atomicAdd(&g_deg[dst[e]], 1);
}
__global__ void scan_kernel() {
    __shared__ int s[1024];
    int t = threadIdx.x;
    int base = t * 8;
    int local[8];
    int run = 0;
#pragma unroll
    for (int i = 0; i < 8; i++) { local[i] = run; run += g_deg[base + i]; }
    s[t] = run;
    __syncthreads();
    for (int o = 1; o < 1024; o <<= 1) {
        int v = (t >= o) ? s[t - o] : 0;
        __syncthreads();
        s[t] += v;
        __syncthreads();
    }
    int prev = (t == 0) ? 0 : s[t - 1];
#pragma unroll
    for (int i = 0; i < 8; i++) g_off[base + i] = prev + local[i];
    if (t == 1023) g_off[NNODES] = s[1023];
}
__global__ void scatter_kernel(const int* __restrict__ dst) {
    int e = blockIdx.x * blockDim.x + threadIdx.x;
    if (e < NEDGES) {
        int d = dst[e];
        int p = atomicAdd(&g_cur[d], 1);
        g_eid[g_off[d] + p] = e;
    }
}
// Deterministic segment ordering: insertion-sort each dst's edge list (avg 8 edges).
// Makes all downstream fp32 summation orders run-to-run identical -> rel_err is frozen.
__global__ void sort_eid_kernel() {
    int d = blockIdx.x * blockDim.x + threadIdx.x;
    if (d >= NNODES) return;
    int s0 = g_off[d], s1 = g_off[d + 1];
    for (int i = s0 + 1; i < s1; i++) {
        int v = g_eid[i];
        int j = i - 1;
        while (j >= s0 && g_eid[j] > v) { g_eid[j + 1] = g_eid[j]; j--; }
        g_eid[j + 1] = v;
    }
}

// ---------------- fp16 tensor-core GEMM ----------------
// C[M,N] tile = A[M, k0:k0+kLen] @ Bt[k0:k0+kLen]^T.  A, Bt row-major, row stride lda.
// Block 128x128, 4 warps (2x2), warp tile 64x64.  K-tile 64, 3-stage cp.async, ldmatrix.
// smem: rows of 64 halves (exactly 128B), XOR swizzle: off(r,c) = r*64 + ((c^(r&7))*8) halves.
//   - cp.async stores: per 8-lane phase, one row, chunks 0..7 -> banks (c^r) distinct.
//   - LDSM: 8 consecutive rows at fixed chunk -> banks distinct.
#define KT 64
#define HG_OPH  (128 * KT)                 // halves per operand per stage = 8192
#define HG_STG  (2 * HG_OPH)               // halves per stage (A + B) = 16384
#define HG_SMEM (3 * HG_STG * 2)           // bytes = 98304

__device__ __forceinline__ int sw_off(int r, int c) {   // halves
    return r * KT + ((c ^ (r & 7)) << 3);
}

__global__ void __launch_bounds__(128, 2)
hgemm(const __half* __restrict__ A, const __half* __restrict__ Bt,
      float* __restrict__ Cf, __half* __restrict__ Ch,
      int lda, int kLen, int N)
{
    extern __shared__ __half hs[];

    const int tid = threadIdx.x, wid = tid >> 5, lane = tid & 31;
    const int bn = blockIdx.x, bm = blockIdx.y, bz = blockIdx.z;
    const int k0 = bz * kLen;
    const int wm = (wid & 1) * 64;
    const int wn = (wid >> 1) * 64;
    const int g = lane >> 2, tg = lane & 3;

    const __half* Ag = A + (size_t)(bm * 128) * lda + k0;
    const __half* Bg = Bt + (size_t)(bn * 128) * lda + k0;

    float acc[32][4] = {};
    const int T = kLen / KT;

    auto load_tile = [&](int t) {
        int st = t % 3;
        __half* As = hs + st * HG_STG;
        __half* Bs = As + HG_OPH;
        int kk = t * KT;
        // 1024 chunks per operand (128 rows x 8), 8 per thread
#pragma unroll
        for (int i = 0; i < 8; i++) {
            int ci = tid + i * 128;
            int r = ci >> 3, c = ci & 7;
            int off = sw_off(r, c);
            const size_t go = (size_t)r * lda + kk + c * 8;
            cp16(smem_u32(&As[off]), Ag + go);
            cp16(smem_u32(&Bs[off]), Bg + go);
        }
        asm volatile("cp.async.commit_group;");
    };

    load_tile(0);
    if (T > 1) load_tile(1);

    // ldmatrix lane roles
    const int a_r = lane & 15;             // row within 16-row mi tile
    const int a_c = lane >> 4;             // which 8-half chunk of the kc pair
    const int b_r = ((lane >> 4) << 3) + (lane & 7);
    const int b_c = (lane >> 3) & 1;

    for (int t = 0; t < T; t++) {
        asm volatile("cp.async.wait_group 1;");
        __syncthreads();
        if (t + 2 < T) load_tile(t + 2);

        const __half* Ab = hs + (t % 3) * HG_STG;
        const __half* Bb = Ab + HG_OPH;
#pragma unroll
        for (int kc = 0; kc < 4; kc++) {            // 4 x k16 per K-tile of 64
            uint32_t a[4][4], b[8][2];
#pragma unroll
            for (int mi = 0; mi < 4; mi++) {
                uint32_t ad = smem_u32(&Ab[sw_off(wm + mi * 16 + a_r, kc * 2 + a_c)]);
                LDSM_X4(a[mi], ad);
            }
#pragma unroll
            for (int p = 0; p < 4; p++) {
                uint32_t br[4];
                uint32_t bd = smem_u32(&Bb[sw_off(wn + p * 16 + b_r, kc * 2 + b_c)]);
                LDSM_X4(br, bd);
                b[2 * p][0] = br[0]; b[2 * p][1] = br[1];
                b[2 * p + 1][0] = br[2]; b[2 * p + 1][1] = br[3];
            }
#pragma unroll
            for (int mi = 0; mi < 4; mi++)
#pragma unroll
                for (int ni = 0; ni < 8; ni++)
                    MMA_F16(acc[mi * 8 + ni], a[mi], b[ni]);
        }
        __syncthreads();
    }

    // epilogue
    if (Ch) {
#pragma unroll
        for (int mi = 0; mi < 4; mi++) {
            int r0 = bm * 128 + wm + mi * 16 + g;
#pragma unroll
            for (int ni = 0; ni < 8; ni++) {
                int c = bn * 128 + wn + ni * 8 + tg * 2;
                __half* p = Ch + (size_t)r0 * N + c;
                __half2 v0 = __floats2half2_rn(acc[mi * 8 + ni][0], acc[mi * 8 + ni][1]);
                __half2 v1 = __floats2half2_rn(acc[mi * 8 + ni][2], acc[mi * 8 + ni][3]);
                *(__half2*)p = v0;
                *(__half2*)(p + (size_t)8 * N) = v1;
            }
        }
    } else {
        float* Cp = Cf + (size_t)bz * NNODES * DHID;
#pragma unroll
        for (int mi = 0; mi < 4; mi++) {
            int r0 = bm * 128 + wm + mi * 16 + g;
#pragma unroll
            for (int ni = 0; ni < 8; ni++) {
                int c = bn * 128 + wn + ni * 8 + tg * 2;
                float* p = Cp + (size_t)r0 * N + c;
                *(float2*)p = make_float2(acc[mi * 8 + ni][0], acc[mi * 8 + ni][1]);
                *(float2*)(p + (size_t)8 * N) = make_float2(acc[mi * 8 + ni][2], acc[mi * 8 + ni][3]);
            }
        }
    }
}

// ---------------- per-(node,head) attention coefficients (fp16 h) ----------------
__global__ void alphas_h_kernel(const __half* __restrict__ h,
                                const float* __restrict__ a_s, const float* __restrict__ a_d,
                                float* __restrict__ out_s, float* __restrict__ out_d,
                                int H, int C)
{
    int w = (blockIdx.x * blockDim.x + threadIdx.x) >> 5;
    int lane = threadIdx.x & 31;
    if (w >= NNODES * H) return;
    int n = w / H, hd = w % H;
    const __half* hp = h + (size_t)n * H * C + (size_t)hd * C;
    const float* asp = a_s + (size_t)hd * C;
    const float* adp = a_d + (size_t)hd * C;
    float ss = 0.f, sd = 0.f;
    for (int c = lane; c < C; c += 32) {
        float v = __half2float(hp[c]);
        ss += v * asp[c];
        sd += v * adp[c];
    }
#pragma unroll
    for (int o = 16; o; o >>= 1) {
        ss += __shfl_down_sync(0xffffffffu, ss, o);
        sd += __shfl_down_sync(0xffffffffu, sd, o);
    }
    if (lane == 0) { out_s[w] = ss; out_d[w] = sd; }
}

// ---------------- split-K reduce + layer-2 alphas (fused) ----------------
__global__ void reduce_alphas2_kernel(const float* __restrict__ part,
                                      float* __restrict__ h2,
                                      const float* __restrict__ a_s, const float* __restrict__ a_d,
                                      float* __restrict__ out_s, float* __restrict__ out_d)
{
    int w = (blockIdx.x * blockDim.x + threadIdx.x) >> 5;
    int lane = threadIdx.x & 31;
    if (w >= NNODES) return;
    const size_t base = (size_t)w * DHID;
    const size_t pstride = (size_t)NNODES * DHID;
    float ss = 0.f, sd = 0.f;
    for (int c = lane; c < DHID; c += 32) {
        float s = part[base + c] + part[pstride + base + c] + part[2 * pstride + base + c];
        h2[base + c] = s;
        ss += s * a_s[c];
        sd += s * a_d[c];
    }
#pragma unroll
    for (int o = 16; o; o >>= 1) {
        ss += __shfl_down_sync(0xffffffffu, ss, o);
        sd += __shfl_down_sync(0xffffffffu, sd, o);
    }
    if (lane == 0) { out_s[w] = ss; out_d[w] = sd; }
}

// ---------------- per-(dst,head) segment softmax ----------------
__global__ void softmax_kernel(const int* __restrict__ src,
                               const float* __restrict__ as, const float* __restrict__ ad,
                               float* __restrict__ alpha, int H)
{
    int idx = blockIdx.x * blockDim.x + threadIdx.x;
    if (idx >= NNODES * H) return;
    int d = idx / H, hd = idx % H;
    int s0 = g_off[d], s1 = g_off[d + 1];
    if (s0 == s1) return;
    float adv = ad[idx];

    float m = -1e30f;
    for (int i = s0; i < s1; i++) {
        int e = g_eid[i];
        float x = as[src[e] * H + hd] + adv;
        x = (x > 0.f) ? x : NEG_SLOPE * x;
        m = fmaxf(m, x);
    }
    float sum = 0.f;
    for (int i = s0; i < s1; i++) {
        int e = g_eid[i];
        float x = as[src[e] * H + hd] + adv;
        x = (x > 0.f) ? x : NEG_SLOPE * x;
        float w = __expf(x - m);
        alpha[(size_t)e * H + hd] = w;
        sum += w;
    }
    float inv = 1.f / (sum + EPSV);
    for (int i = s0; i < s1; i++) {
        int e = g_eid[i];
        alpha[(size_t)e * H + hd] *= inv;
    }
}

// ---------------- layer-1 aggregation: fp16 gather, fp16 out ----------------
__global__ void __launch_bounds__(192)
aggregate1_kernel(const int* __restrict__ src, const float* __restrict__ alpha,
                  const __half* __restrict__ h, __half* __restrict__ out_h,
                  const float* __restrict__ bias)
{
    int d  = blockIdx.x % NNODES;
    int hd = blockIdx.x / NNODES;
    int t  = threadIdx.x;
    int s0 = g_off[d], s1 = g_off[d + 1];
    const size_t rs = (size_t)H1N * DHID;

    float4 acc = make_float4(0.f, 0.f, 0.f, 0.f);
    for (int i = s0; i < s1; i++) {
        int e = g_eid[i];
        float a = alpha[(size_t)e * H1N + hd];
        uint2 u = *(((const uint2*)(h + (size_t)src[e] * rs + (size_t)hd * DHID)) + t);
        __half2 v0 = *(__half2*)&u.x;
        __half2 v1 = *(__half2*)&u.y;
        float2 f0 = __half22float2(v0);
        float2 f1 = __half22float2(v1);
        acc.x += a * f0.x; acc.y += a * f0.y; acc.z += a * f1.x; acc.w += a * f1.y;
    }
    float4 b = *(((const float4*)(bias + (size_t)hd * DHID)) + t);
    acc.x += b.x; acc.y += b.y; acc.z += b.z; acc.w += b.w;
    acc.x = (acc.x > 0.f) ? acc.x : expm1f(acc.x);
    acc.y = (acc.y > 0.f) ? acc.y : expm1f(acc.y);
    acc.z = (acc.z > 0.f) ? acc.z : expm1f(acc.z);
    acc.w = (acc.w > 0.f) ? acc.w : expm1f(acc.w);
    __half2 h0 = __floats2half2_rn(acc.x, acc.y);
    __half2 h1 = __floats2half2_rn(acc.z, acc.w);
    uint2 u; u.x = *(uint32_t*)&h0; u.y = *(uint32_t*)&h1;
    *(((uint2*)(out_h + (size_t)d * rs + (size_t)hd * DHID)) + t) = u;
}

// ---------------- layer-2 aggregation: fp32 gather, fp32 out ----------------
__global__ void __launch_bounds__(192)
aggregate2_kernel(const int* __restrict__ src, const float* __restrict__ alpha,
                  const float* __restrict__ h, float* __restrict__ out,
                  const float* __restrict__ bias)
{
    int d = blockIdx.x;
    int t = threadIdx.x;
    int s0 = g_off[d], s1 = g_off[d + 1];

    float4 acc = make_float4(0.f, 0.f, 0.f, 0.f);
    for (int i = s0; i < s1; i++) {
        int e = g_eid[i];
        float a = alpha[e];
        float4 v = *(((const float4*)(h + (size_t)src[e] * DHID)) + t);
        acc.x += a * v.x; acc.y += a * v.y; acc.z += a * v.z; acc.w += a * v.w;
    }
    float4 b = *(((const float4*)bias) + t);
    acc.x += b.x; acc.y += b.y; acc.z += b.z; acc.w += b.w;
    *(((float4*)(out + (size_t)d * DHID)) + t) = acc;
}

// ---------------- launch ----------------
extern "C" void kernel_launch(void* const* d_in, const int* in_sizes, int n_in,
                              void* d_out, int out_size)
{
    const float* x    = (const float*)d_in[0];
    const float* W1   = (const float*)d_in[1];
    const float* a_s1 = (const float*)d_in[2];
    const float* a_d1 = (const float*)d_in[3];
    const float* b1   = (const float*)d_in[4];
    const float* W2   = (const float*)d_in[5];
    const float* a_s2 = (const float*)d_in[6];
    const float* a_d2 = (const float*)d_in[7];
    const float* b2   = (const float*)d_in[8];
    const int* edges  = (const int*)d_in[9];
    const int* src = edges;
    const int* dst = edges + NEDGES;
    float* out = (float*)d_out;

    float *part, *h2, *as1, *ad1, *as2, *ad2, *al1, *al2;
    __half *h1h, *xh, *o1h, *w1th, *w2th;
    cudaGetSymbolAddress((void**)&h1h,  g_h1h);
    cudaGetSymbolAddress((void**)&part, g_part);
    cudaGetSymbolAddress((void**)&h2,   g_h2);
    cudaGetSymbolAddress((void**)&xh,   g_xh);
    cudaGetSymbolAddress((void**)&o1h,  g_o1h);
    cudaGetSymbolAddress((void**)&w1th, g_w1th);
    cudaGetSymbolAddress((void**)&w2th, g_w2th);
    cudaGetSymbolAddress((void**)&as1,  g_as1);
    cudaGetSymbolAddress((void**)&ad1,  g_ad1);
    cudaGetSymbolAddress((void**)&as2,  g_as2);
    cudaGetSymbolAddress((void**)&ad2,  g_ad2);
    cudaGetSymbolAddress((void**)&al1,  g_alpha1);
    cudaGetSymbolAddress((void**)&al2,  g_alpha2);

    cudaFuncSetAttribute(hgemm, cudaFuncAttributeMaxDynamicSharedMemorySize, HG_SMEM);

    dim3 tblk(32, 8);

    // 0: x -> fp16
    f2h_kernel<<<(NNODES * DIN / 4 + 255) / 256, 256>>>(x, xh, NNODES * DIN / 4);
    // 1: W1 [768,6144] -> W1^T fp16 [6144,768]
    {
        dim3 gt((H1N * DHID) / 32, DIN / 32);
        transpose_h_kernel<<<gt, tblk>>>(W1, w1th, DIN, H1N * DHID);
    }
    // 2: W2 [6144,768] -> W2^T fp16 [768,6144]
    {
        dim3 gt(DHID / 32, (H1N * DHID) / 32);
        transpose_h_kernel<<<gt, tblk>>>(W2, w2th, H1N * DHID, DHID);
    }
    // 3: GEMM1 (ncu capture slot)  h1h = fp16(x @ W1)  [8192, 6144]
    {
        dim3 grid((H1N * DHID) / 128, NNODES / 128, 1);   // (48, 64)
        hgemm<<<grid, 128, HG_SMEM>>>(xh, w1th, nullptr, h1h, DIN, DIN, H1N * DHID);
    }
    // CSR build (+ deterministic segment ordering)
    zero_counts_kernel<<<(NNODES + 255) / 256, 256>>>();
    count_kernel<<<(NEDGES + 255) / 256, 256>>>(dst);
    scan_kernel<<<1, 1024>>>();
    scatter_kernel<<<(NEDGES + 255) / 256, 256>>>(dst);
    sort_eid_kernel<<<(NNODES + 255) / 256, 256>>>();
    // layer-1 attention + aggregation (fp16 h1, fp16 o1)
    alphas_h_kernel<<<(NNODES * H1N * 32 + 255) / 256, 256>>>(h1h, a_s1, a_d1, as1, ad1, H1N, DHID);
    softmax_kernel<<<(NNODES * H1N + 255) / 256, 256>>>(src, as1, ad1, al1, H1N);
    aggregate1_kernel<<<NNODES * H1N, DHID / 4>>>(src, al1, h1h, o1h, b1);
    // GEMM2 split-K 3
    {
        dim3 grid((H2N * DHID) / 128, NNODES / 128, SPLITK);   // (6, 64, 3)
        hgemm<<<grid, 128, HG_SMEM>>>(o1h, w2th, part, nullptr, H1N * DHID, K2CHUNK, H2N * DHID);
    }
    // split-K reduce + layer-2 alphas (fused)
    reduce_alphas2_kernel<<<(NNODES * 32 + 255) / 256, 256>>>(part, h2, a_s2, a_d2, as2, ad2);
    softmax_kernel<<<(NNODES + 255) / 256, 256>>>(src, as2, ad2, al2, H2N);
    aggregate2_kernel<<<NNODES, DHID / 4>>>(src, al2, h2, out, b2);
}

// round 12
// speedup vs baseline: 1.7293x; 1.0981x over previous
#include <cuda_runtime.h>
#include <cuda_fp16.h>
#include <math.h>
#include <cstdint>

// ---------------- problem constants ----------------
#define NNODES 8192
#define NEDGES 65536
#define DIN    768
#define DHID   768
#define H1N    8
#define H2N    1
#define NEG_SLOPE 0.2f
#define EPSV 1e-16f
#define SPLITK 3
#define K2CHUNK ((H1N * DHID) / SPLITK)     // 2048

// ---------------- scratch (device globals; no allocs allowed) ----------------
__device__ __half g_h1h[(size_t)NNODES * (H1N * DHID)];    // x @ W1 fp16 [8192, 6144]
__device__ float  g_part[(size_t)SPLITK * NNODES * DHID];  // GEMM2 split-K partials
__device__ float  g_h2[(size_t)NNODES * DHID];             // o1 @ W2 summed [8192, 768]
__device__ __half g_xh [(size_t)NNODES * DIN];             // x fp16
__device__ __half g_o1h[(size_t)NNODES * (H1N * DHID)];    // elu(agg1+b1) fp16 (GEMM2 A)
__device__ __half g_w1th[(size_t)(H1N * DHID) * DIN];      // W1^T fp16 [6144, 768]
__device__ __half g_w2th[(size_t)DHID * (H1N * DHID)];     // W2^T fp16 [768, 6144]
__device__ float g_as1[NNODES * H1N];
__device__ float g_ad1[NNODES * H1N];
__device__ float g_as2[NNODES];
__device__ float g_ad2[NNODES];
__device__ float g_alpha1[(size_t)NEDGES * H1N];
__device__ float g_alpha2[(size_t)NEDGES];
__device__ int   g_deg[NNODES];
__device__ int   g_cur[NNODES];
__device__ int   g_off[NNODES + 1];
__device__ int   g_eid[NEDGES];

// ---------------- helpers ----------------
__device__ __forceinline__ void cp16(unsigned dst, const void* src) {
    asm volatile("cp.async.cg.shared.global [%0], [%1], 16;" :: "r"(dst), "l"(src));
}
__device__ __forceinline__ uint32_t smem_u32(const void* p) {
    return (uint32_t)__cvta_generic_to_shared(p);
}

#define MMA_F16(d, a, b)                                                               \
    asm volatile(                                                                      \
        "mma.sync.aligned.m16n8k16.row.col.f32.f16.f16.f32 "                           \
        "{%0,%1,%2,%3},{%4,%5,%6,%7},{%8,%9},{%0,%1,%2,%3};"                           \
        : "+f"((d)[0]), "+f"((d)[1]), "+f"((d)[2]), "+f"((d)[3])                       \
        : "r"((a)[0]), "r"((a)[1]), "r"((a)[2]), "r"((a)[3]), "r"((b)[0]), "r"((b)[1]))

#define LDSM_X4(r, addr)                                                               \
    asm volatile("ldmatrix.sync.aligned.m8n8.x4.shared.b16 {%0,%1,%2,%3}, [%4];"       \
        : "=r"((r)[0]), "=r"((r)[1]), "=r"((r)[2]), "=r"((r)[3]) : "r"(addr))

// ---------------- fp32 -> fp16 convert ----------------
__global__ void f2h_kernel(const float* __restrict__ in, __half* __restrict__ out, int n4) {
    int i = blockIdx.x * blockDim.x + threadIdx.x;
    if (i < n4) {
        float4 v = ((const float4*)in)[i];
        __half2 h0 = __floats2half2_rn(v.x, v.y);
        __half2 h1 = __floats2half2_rn(v.z, v.w);
        uint2 u;
        u.x = *(uint32_t*)&h0; u.y = *(uint32_t*)&h1;
        ((uint2*)out)[i] = u;
    }
}

// ---------------- transpose + fp16 convert: in [R,C] fp32 -> out [C,R] fp16 ----------------
__global__ void transpose_h_kernel(const float* __restrict__ in, __half* __restrict__ out,
                                   int R, int C)
{
    __shared__ float t[32][33];
    int bx = blockIdx.x * 32, by = blockIdx.y * 32;
#pragma unroll
    for (int i = 0; i < 4; i++)
        t[threadIdx.y + 8 * i][threadIdx.x] =
            in[(size_t)(by + threadIdx.y + 8 * i) * C + bx + threadIdx.x];
    __syncthreads();
#pragma unroll
    for (int i = 0; i < 4; i++)
        out[(size_t)(bx + threadIdx.y + 8 * i) * R + by + threadIdx.x] =
            __float2half_rn(t[threadIdx.x][threadIdx.y + 8 * i]);
}

// ---------------- CSR build ----------------
__global__ void zero_counts_kernel() {
    int i = blockIdx.x * blockDim.x + threadIdx.x;
    if (i < NNODES) { g_deg[i] = 0; g_cur[i] = 0; }
}
__global__ void count_kernel(const int* __restrict__ dst) {
    int e = blockIdx.x * blockDim.x + threadIdx.x;
    if (e < NEDGES) atomicAdd(&g_deg[dst[e]], 1);
}
__global__ void scan_kernel() {
    __shared__ int s[1024];
    int t = threadIdx.x;
    int base = t * 8;
    int local[8];
    int run = 0;
#pragma unroll
    for (int i = 0; i < 8; i++) { local[i] = run; run += g_deg[base + i]; }
    s[t] = run;
    __syncthreads();
    for (int o = 1; o < 1024; o <<= 1) {
        int v = (t >= o) ? s[t - o] : 0;
        __syncthreads();
        s[t] += v;
        __syncthreads();
    }
    int prev = (t == 0) ? 0 : s[t - 1];
#pragma unroll
    for (int i = 0; i < 8; i++) g_off[base + i] = prev + local[i];
    if (t == 1023) g_off[NNODES] = s[1023];
}
__global__ void scatter_kernel(const int* __restrict__ dst) {
    int e = blockIdx.x * blockDim.x + threadIdx.x;
    if (e < NEDGES) {
        int d = dst[e];
        int p = atomicAdd(&g_cur[d], 1);
        g_eid[g_off[d] + p] = e;
    }
}
// Deterministic segment ordering (freezes all downstream fp32 sum orders).
__global__ void sort_eid_kernel() {
    int d = blockIdx.x * blockDim.x + threadIdx.x;
    if (d >= NNODES) return;
    int s0 = g_off[d], s1 = g_off[d + 1];
    for (int i = s0 + 1; i < s1; i++) {
        int v = g_eid[i];
        int j = i - 1;
        while (j >= s0 && g_eid[j] > v) { g_eid[j + 1] = g_eid[j]; j--; }
        g_eid[j + 1] = v;
    }
}

// ---------------- fp16 tensor-core GEMM ----------------
// Block 128x128, 4 warps (2x2), warp tile 64x64.  K-tile 64, 3-stage cp.async, ldmatrix.
// XOR-swizzled smem rows of exactly 128B.
#define KT 64
#define HG_OPH  (128 * KT)
#define HG_STG  (2 * HG_OPH)
#define HG_SMEM (3 * HG_STG * 2)           // 98304 bytes

__device__ __forceinline__ int sw_off(int r, int c) {
    return r * KT + ((c ^ (r & 7)) << 3);
}

__global__ void __launch_bounds__(128, 2)
hgemm(const __half* __restrict__ A, const __half* __restrict__ Bt,
      float* __restrict__ Cf, __half* __restrict__ Ch,
      int lda, int kLen, int N)
{
    extern __shared__ __half hs[];

    const int tid = threadIdx.x, wid = tid >> 5, lane = tid & 31;
    const int bn = blockIdx.x, bm = blockIdx.y, bz = blockIdx.z;
    const int k0 = bz * kLen;
    const int wm = (wid & 1) * 64;
    const int wn = (wid >> 1) * 64;
    const int g = lane >> 2, tg = lane & 3;

    const __half* Ag = A + (size_t)(bm * 128) * lda + k0;
    const __half* Bg = Bt + (size_t)(bn * 128) * lda + k0;

    float acc[32][4] = {};
    const int T = kLen / KT;

    auto load_tile = [&](int t) {
        int st = t % 3;
        __half* As = hs + st * HG_STG;
        __half* Bs = As + HG_OPH;
        int kk = t * KT;
#pragma unroll
        for (int i = 0; i < 8; i++) {
            int ci = tid + i * 128;
            int r = ci >> 3, c = ci & 7;
            int off = sw_off(r, c);
            const size_t go = (size_t)r * lda + kk + c * 8;
            cp16(smem_u32(&As[off]), Ag + go);
            cp16(smem_u32(&Bs[off]), Bg + go);
        }
        asm volatile("cp.async.commit_group;");
    };

    load_tile(0);
    if (T > 1) load_tile(1);

    const int a_r = lane & 15;
    const int a_c = lane >> 4;
    const int b_r = ((lane >> 4) << 3) + (lane & 7);
    const int b_c = (lane >> 3) & 1;

    for (int t = 0; t < T; t++) {
        asm volatile("cp.async.wait_group 1;");
        __syncthreads();
        if (t + 2 < T) load_tile(t + 2);

        const __half* Ab = hs + (t % 3) * HG_STG;
        const __half* Bb = Ab + HG_OPH;
#pragma unroll
        for (int kc = 0; kc < 4; kc++) {
            uint32_t a[4][4], b[8][2];
#pragma unroll
            for (int mi = 0; mi < 4; mi++) {
                uint32_t ad = smem_u32(&Ab[sw_off(wm + mi * 16 + a_r, kc * 2 + a_c)]);
                LDSM_X4(a[mi], ad);
            }
#pragma unroll
            for (int p = 0; p < 4; p++) {
                uint32_t br[4];
                uint32_t bd = smem_u32(&Bb[sw_off(wn + p * 16 + b_r, kc * 2 + b_c)]);
                LDSM_X4(br, bd);
                b[2 * p][0] = br[0]; b[2 * p][1] = br[1];
                b[2 * p + 1][0] = br[2]; b[2 * p + 1][1] = br[3];
            }
#pragma unroll
            for (int mi = 0; mi < 4; mi++)
#pragma unroll
                for (int ni = 0; ni < 8; ni++)
                    MMA_F16(acc[mi * 8 + ni], a[mi], b[ni]);
        }
        __syncthreads();
    }

    if (Ch) {
#pragma unroll
        for (int mi = 0; mi < 4; mi++) {
            int r0 = bm * 128 + wm + mi * 16 + g;
#pragma unroll
            for (int ni = 0; ni < 8; ni++) {
                int c = bn * 128 + wn + ni * 8 + tg * 2;
                __half* p = Ch + (size_t)r0 * N + c;
                __half2 v0 = __floats2half2_rn(acc[mi * 8 + ni][0], acc[mi * 8 + ni][1]);
                __half2 v1 = __floats2half2_rn(acc[mi * 8 + ni][2], acc[mi * 8 + ni][3]);
                *(__half2*)p = v0;
                *(__half2*)(p + (size_t)8 * N) = v1;
            }
        }
    } else {
        float* Cp = Cf + (size_t)bz * NNODES * DHID;
#pragma unroll
        for (int mi = 0; mi < 4; mi++) {
            int r0 = bm * 128 + wm + mi * 16 + g;
#pragma unroll
            for (int ni = 0; ni < 8; ni++) {
                int c = bn * 128 + wn + ni * 8 + tg * 2;
                float* p = Cp + (size_t)r0 * N + c;
                *(float2*)p = make_float2(acc[mi * 8 + ni][0], acc[mi * 8 + ni][1]);
                *(float2*)(p + (size_t)8 * N) = make_float2(acc[mi * 8 + ni][2], acc[mi * 8 + ni][3]);
            }
        }
    }
}

// ---------------- per-(node,head) attention coefficients (fp16 h) ----------------
__global__ void alphas_h_kernel(const __half* __restrict__ h,
                                const float* __restrict__ a_s, const float* __restrict__ a_d,
                                float* __restrict__ out_s, float* __restrict__ out_d,
                                int H, int C)
{
    int w = (blockIdx.x * blockDim.x + threadIdx.x) >> 5;
    int lane = threadIdx.x & 31;
    if (w >= NNODES * H) return;
    int n = w / H, hd = w % H;
    const __half* hp = h + (size_t)n * H * C + (size_t)hd * C;
    const float* asp = a_s + (size_t)hd * C;
    const float* adp = a_d + (size_t)hd * C;
    float ss = 0.f, sd = 0.f;
    for (int c = lane; c < C; c += 32) {
        float v = __half2float(hp[c]);
        ss += v * asp[c];
        sd += v * adp[c];
    }
#pragma unroll
    for (int o = 16; o; o >>= 1) {
        ss += __shfl_down_sync(0xffffffffu, ss, o);
        sd += __shfl_down_sync(0xffffffffu, sd, o);
    }
    if (lane == 0) { out_s[w] = ss; out_d[w] = sd; }
}

// ---------------- split-K reduce + layer-2 alphas (fused) ----------------
__global__ void reduce_alphas2_kernel(const float* __restrict__ part,
                                      float* __restrict__ h2,
                                      const float* __restrict__ a_s, const float* __restrict__ a_d,
                                      float* __restrict__ out_s, float* __restrict__ out_d)
{
    int w = (blockIdx.x * blockDim.x + threadIdx.x) >> 5;
    int lane = threadIdx.x & 31;
    if (w >= NNODES) return;
    const size_t base = (size_t)w * DHID;
    const size_t pstride = (size_t)NNODES * DHID;
    float ss = 0.f, sd = 0.f;
    for (int c = lane; c < DHID; c += 32) {
        float s = part[base + c] + part[pstride + base + c] + part[2 * pstride + base + c];
        h2[base + c] = s;
        ss += s * a_s[c];
        sd += s * a_d[c];
    }
#pragma unroll
    for (int o = 16; o; o >>= 1) {
        ss += __shfl_down_sync(0xffffffffu, ss, o);
        sd += __shfl_down_sync(0xffffffffu, sd, o);
    }
    if (lane == 0) { out_s[w] = ss; out_d[w] = sd; }
}

// ---------------- per-(dst,head) segment softmax ----------------
__global__ void softmax_kernel(const int* __restrict__ src,
                               const float* __restrict__ as, const float* __restrict__ ad,
                               float* __restrict__ alpha, int H)
{
    int idx = blockIdx.x * blockDim.x + threadIdx.x;
    if (idx >= NNODES * H) return;
    int d = idx / H, hd = idx % H;
    int s0 = g_off[d], s1 = g_off[d + 1];
    if (s0 == s1) return;
    float adv = ad[idx];

    float m = -1e30f;
    for (int i = s0; i < s1; i++) {
        int e = g_eid[i];
        float x = as[src[e] * H + hd] + adv;
        x = (x > 0.f) ? x : NEG_SLOPE * x;
        m = fmaxf(m, x);
    }
    float sum = 0.f;
    for (int i = s0; i < s1; i++) {
        int e = g_eid[i];
        float x = as[src[e] * H + hd] + adv;
        x = (x > 0.f) ? x : NEG_SLOPE * x;
        float w = __expf(x - m);
        alpha[(size_t)e * H + hd] = w;
        sum += w;
    }
    float inv = 1.f / (sum + EPSV);
    for (int i = s0; i < s1; i++) {
        int e = g_eid[i];
        alpha[(size_t)e * H + hd] *= inv;
    }
}

// ---------------- layer-1 aggregation: one block per node, all heads ----------------
// 256 threads: thread t -> head t/32, halves [ (t%32)*24, +24 ) within the head (3x uint4).
// Per-element edge-sum order identical to previous versions (same sorted eid loop).
__global__ void __launch_bounds__(256)
aggregate1_kernel(const int* __restrict__ src, const float* __restrict__ alpha,
                  const __half* __restrict__ h, __half* __restrict__ out_h,
                  const float* __restrict__ bias)
{
    int d  = blockIdx.x;
    int t  = threadIdx.x;
    int hd = t >> 5;
    size_t rowoff = (size_t)hd * DHID + (size_t)(t & 31) * 24;   // halves; 48B -> 16B aligned
    int s0 = g_off[d], s1 = g_off[d + 1];
    const size_t rs = (size_t)H1N * DHID;

    float acc[24];
#pragma unroll
    for (int j = 0; j < 24; j++) acc[j] = 0.f;

    for (int i = s0; i < s1; i++) {
        int e = g_eid[i];
        float a = alpha[(size_t)e * H1N + hd];
        const uint4* p = (const uint4*)(h + (size_t)src[e] * rs + rowoff);
#pragma unroll
        for (int j = 0; j < 3; j++) {
            uint4 u = p[j];
            const __half2* hh = (const __half2*)&u;
#pragma unroll
            for (int k = 0; k < 4; k++) {
                float2 f = __half22float2(hh[k]);
                acc[j * 8 + k * 2]     += a * f.x;
                acc[j * 8 + k * 2 + 1] += a * f.y;
            }
        }
    }

    const float* bp = bias + rowoff;
    __half* op = out_h + (size_t)d * rs + rowoff;
#pragma unroll
    for (int j = 0; j < 3; j++) {
        uint4 u;
        __half2* hh = (__half2*)&u;
#pragma unroll
        for (int k = 0; k < 4; k++) {
            float v0 = acc[j * 8 + k * 2]     + bp[j * 8 + k * 2];
            float v1 = acc[j * 8 + k * 2 + 1] + bp[j * 8 + k * 2 + 1];
            v0 = (v0 > 0.f) ? v0 : expm1f(v0);
            v1 = (v1 > 0.f) ? v1 : expm1f(v1);
            hh[k] = __floats2half2_rn(v0, v1);
        }
        ((uint4*)op)[j] = u;
    }
}

// ---------------- layer-2 aggregation: fp32 gather, fp32 out ----------------
__global__ void __launch_bounds__(192)
aggregate2_kernel(const int* __restrict__ src, const float* __restrict__ alpha,
                  const float* __restrict__ h, float* __restrict__ out,
                  const float* __restrict__ bias)
{
    int d = blockIdx.x;
    int t = threadIdx.x;
    int s0 = g_off[d], s1 = g_off[d + 1];

    float4 acc = make_float4(0.f, 0.f, 0.f, 0.f);
    for (int i = s0; i < s1; i++) {
        int e = g_eid[i];
        float a = alpha[e];
        float4 v = *(((const float4*)(h + (size_t)src[e] * DHID)) + t);
        acc.x += a * v.x; acc.y += a * v.y; acc.z += a * v.z; acc.w += a * v.w;
    }
    float4 b = *(((const float4*)bias) + t);
    acc.x += b.x; acc.y += b.y; acc.z += b.z; acc.w += b.w;
    *(((float4*)(out + (size_t)d * DHID)) + t) = acc;
}

// ---------------- launch ----------------
extern "C" void kernel_launch(void* const* d_in, const int* in_sizes, int n_in,
                              void* d_out, int out_size)
{
    const float* x    = (const float*)d_in[0];
    const float* W1   = (const float*)d_in[1];
    const float* a_s1 = (const float*)d_in[2];
    const float* a_d1 = (const float*)d_in[3];
    const float* b1   = (const float*)d_in[4];
    const float* W2   = (const float*)d_in[5];
    const float* a_s2 = (const float*)d_in[6];
    const float* a_d2 = (const float*)d_in[7];
    const float* b2   = (const float*)d_in[8];
    const int* edges  = (const int*)d_in[9];
    const int* src = edges;
    const int* dst = edges + NEDGES;
    float* out = (float*)d_out;

    float *part, *h2, *as1, *ad1, *as2, *ad2, *al1, *al2;
    __half *h1h, *xh, *o1h, *w1th, *w2th;
    cudaGetSymbolAddress((void**)&h1h,  g_h1h);
    cudaGetSymbolAddress((void**)&part, g_part);
    cudaGetSymbolAddress((void**)&h2,   g_h2);
    cudaGetSymbolAddress((void**)&xh,   g_xh);
    cudaGetSymbolAddress((void**)&o1h,  g_o1h);
    cudaGetSymbolAddress((void**)&w1th, g_w1th);
    cudaGetSymbolAddress((void**)&w2th, g_w2th);
    cudaGetSymbolAddress((void**)&as1,  g_as1);
    cudaGetSymbolAddress((void**)&ad1,  g_ad1);
    cudaGetSymbolAddress((void**)&as2,  g_as2);
    cudaGetSymbolAddress((void**)&ad2,  g_ad2);
    cudaGetSymbolAddress((void**)&al1,  g_alpha1);
    cudaGetSymbolAddress((void**)&al2,  g_alpha2);

    cudaFuncSetAttribute(hgemm, cudaFuncAttributeMaxDynamicSharedMemorySize, HG_SMEM);

    // Side stream + events, created once on the (uncaptured) first call.
    // Same launches every call -> deterministic work; no device memory involved.
    static cudaStream_t s2 = nullptr;
    static cudaEvent_t evFork = nullptr, evJoin = nullptr;
    if (!s2) {
        cudaStreamCreateWithFlags(&s2, cudaStreamNonBlocking);
        cudaEventCreateWithFlags(&evFork, cudaEventDisableTiming);
        cudaEventCreateWithFlags(&evJoin, cudaEventDisableTiming);
    }

    dim3 tblk(32, 8);

    // ---- fork: CSR chain + W2 transpose on side stream ----
    cudaEventRecord(evFork, 0);
    cudaStreamWaitEvent(s2, evFork, 0);
    zero_counts_kernel<<<(NNODES + 255) / 256, 256, 0, s2>>>();
    count_kernel<<<(NEDGES + 255) / 256, 256, 0, s2>>>(dst);
    scan_kernel<<<1, 1024, 0, s2>>>();
    scatter_kernel<<<(NEDGES + 255) / 256, 256, 0, s2>>>(dst);
    sort_eid_kernel<<<(NNODES + 255) / 256, 256, 0, s2>>>();
    {
        dim3 gt(DHID / 32, (H1N * DHID) / 32);
        transpose_h_kernel<<<gt, tblk, 0, s2>>>(W2, w2th, H1N * DHID, DHID);
    }
    cudaEventRecord(evJoin, s2);

    // ---- main chain ----
    f2h_kernel<<<(NNODES * DIN / 4 + 255) / 256, 256>>>(x, xh, NNODES * DIN / 4);
    {
        dim3 gt((H1N * DHID) / 32, DIN / 32);
        transpose_h_kernel<<<gt, tblk>>>(W1, w1th, DIN, H1N * DHID);
    }
    {
        dim3 grid((H1N * DHID) / 128, NNODES / 128, 1);   // (48, 64)
        hgemm<<<grid, 128, HG_SMEM>>>(xh, w1th, nullptr, h1h, DIN, DIN, H1N * DHID);
    }
    alphas_h_kernel<<<(NNODES * H1N * 32 + 255) / 256, 256>>>(h1h, a_s1, a_d1, as1, ad1, H1N, DHID);

    // join: softmax needs CSR (+sort); GEMM2 later needs W2t
    cudaStreamWaitEvent(0, evJoin, 0);

    softmax_kernel<<<(NNODES * H1N + 255) / 256, 256>>>(src, as1, ad1, al1, H1N);
    aggregate1_kernel<<<NNODES, 256>>>(src, al1, h1h, o1h, b1);
    {
        dim3 grid((H2N * DHID) / 128, NNODES / 128, SPLITK);   // (6, 64, 3)
        hgemm<<<grid, 128, HG_SMEM>>>(o1h, w2th, part, nullptr, H1N * DHID, K2CHUNK, H2N * DHID);
    }
    reduce_alphas2_kernel<<<(NNODES * 32 + 255) / 256, 256>>>(part, h2, a_s2, a_d2, as2, ad2);
    softmax_kernel<<<(NNODES + 255) / 256, 256>>>(src, as2, ad2, al2, H2N);
    aggregate2_kernel<<<NNODES, DHID / 4>>>(src, al2, h2, out, b2);
}

// round 13
// speedup vs baseline: 1.7332x; 1.0023x over previous
#include <cuda_runtime.h>
#include <cuda_fp16.h>
#include <math.h>
#include <cstdint>

// ---------------- problem constants ----------------
#define NNODES 8192
#define NEDGES 65536
#define DIN    768
#define DHID   768
#define H1N    8
#define H2N    1
#define NEG_SLOPE 0.2f
#define EPSV 1e-16f
#define SPLITK 3
#define K2CHUNK ((H1N * DHID) / SPLITK)     // 2048

// ---------------- scratch (device globals; no allocs allowed) ----------------
__device__ __half g_h1h[(size_t)NNODES * (H1N * DHID)];    // x @ W1 fp16 [8192, 6144]
__device__ float  g_part[(size_t)SPLITK * NNODES * DHID];  // GEMM2 split-K partials
__device__ float  g_h2[(size_t)NNODES * DHID];             // o1 @ W2 summed [8192, 768]
__device__ __half g_xh [(size_t)NNODES * DIN];             // x fp16
__device__ __half g_o1h[(size_t)NNODES * (H1N * DHID)];    // elu(agg1+b1) fp16 (GEMM2 A)
__device__ __half g_w1th[(size_t)(H1N * DHID) * DIN];      // W1^T fp16 [6144, 768]
__device__ __half g_w2th[(size_t)DHID * (H1N * DHID)];     // W2^T fp16 [768, 6144]
__device__ float g_as1[NNODES * H1N];
__device__ float g_ad1[NNODES * H1N];
__device__ float g_as2[NNODES];
__device__ float g_ad2[NNODES];
__device__ float g_alpha1[(size_t)NEDGES * H1N];
__device__ float g_alpha2[(size_t)NEDGES];
__device__ int   g_deg[NNODES];
__device__ int   g_cur[NNODES];
__device__ int   g_off[NNODES + 1];
__device__ int   g_eid[NEDGES];

// ---------------- helpers ----------------
__device__ __forceinline__ void cp16(unsigned dst, const void* src) {
    asm volatile("cp.async.cg.shared.global [%0], [%1], 16;" :: "r"(dst), "l"(src));
}
__device__ __forceinline__ uint32_t smem_u32(const void* p) {
    return (uint32_t)__cvta_generic_to_shared(p);
}

#define MMA_F16(d, a, b)                                                               \
    asm volatile(                                                                      \
        "mma.sync.aligned.m16n8k16.row.col.f32.f16.f16.f32 "                           \
        "{%0,%1,%2,%3},{%4,%5,%6,%7},{%8,%9},{%0,%1,%2,%3};"                           \
        : "+f"((d)[0]), "+f"((d)[1]), "+f"((d)[2]), "+f"((d)[3])                       \
        : "r"((a)[0]), "r"((a)[1]), "r"((a)[2]), "r"((a)[3]), "r"((b)[0]), "r"((b)[1]))

#define LDSM_X4(r, addr)                                                               \
    asm volatile("ldmatrix.sync.aligned.m8n8.x4.shared.b16 {%0,%1,%2,%3}, [%4];"       \
        : "=r"((r)[0]), "=r"((r)[1]), "=r"((r)[2]), "=r"((r)[3]) : "r"(addr))

// ---------------- fp32 -> fp16 convert ----------------
__global__ void f2h_kernel(const float* __restrict__ in, __half* __restrict__ out, int n4) {
    int i = blockIdx.x * blockDim.x + threadIdx.x;
    if (i < n4) {
        float4 v = ((const float4*)in)[i];
        __half2 h0 = __floats2half2_rn(v.x, v.y);
        __half2 h1 = __floats2half2_rn(v.z, v.w);
        uint2 u;
        u.x = *(uint32_t*)&h0; u.y = *(uint32_t*)&h1;
        ((uint2*)out)[i] = u;
    }
}

// ---------------- transpose + fp16 convert: in [R,C] fp32 -> out [C,R] fp16 ----------------
__global__ void transpose_h_kernel(const float* __restrict__ in, __half* __restrict__ out,
                                   int R, int C)
{
    __shared__ float t[32][33];
    int bx = blockIdx.x * 32, by = blockIdx.y * 32;
#pragma unroll
    for (int i = 0; i < 4; i++)
        t[threadIdx.y + 8 * i][threadIdx.x] =
            in[(size_t)(by + threadIdx.y + 8 * i) * C + bx + threadIdx.x];
    __syncthreads();
#pragma unroll
    for (int i = 0; i < 4; i++)
        out[(size_t)(bx + threadIdx.y + 8 * i) * R + by + threadIdx.x] =
            __float2half_rn(t[threadIdx.x][threadIdx.y + 8 * i]);
}

// ---------------- CSR build ----------------
__global__ void zero_counts_kernel() {
    int i = blockIdx.x * blockDim.x + threadIdx.x;
    if (i < NNODES) { g_deg[i] = 0; g_cur[i] = 0; }
}
__global__ void count_kernel(const int* __restrict__ dst) {
    int e = blockIdx.x * blockDim.x + threadIdx.x;
    if (e < NEDGES) atomicAdd(&g_deg[dst[e]], 1);
}
__global__ void scan_kernel() {
    __shared__ int s[1024];
    int t = threadIdx.x;
    int base = t * 8;
    int local[8];
    int run = 0;
#pragma unroll
    for (int i = 0; i < 8; i++) { local[i] = run; run += g_deg[base + i]; }
    s[t] = run;
    __syncthreads();
    for (int o = 1; o < 1024; o <<= 1) {
        int v = (t >= o) ? s[t - o] : 0;
        __syncthreads();
        s[t] += v;
        __syncthreads();
    }
    int prev = (t == 0) ? 0 : s[t - 1];
#pragma unroll
    for (int i = 0; i < 8; i++) g_off[base + i] = prev + local[i];
    if (t == 1023) g_off[NNODES] = s[1023];
}
__global__ void scatter_kernel(const int* __restrict__ dst) {
    int e = blockIdx.x * blockDim.x + threadIdx.x;
    if (e < NEDGES) {
        int d = dst[e];
        int p = atomicAdd(&g_cur[d], 1);
        g_eid[g_off[d] + p] = e;
    }
}
// Deterministic segment ordering (freezes all downstream fp32 sum orders).
__global__ void sort_eid_kernel() {
    int d = blockIdx.x * blockDim.x + threadIdx.x;
    if (d >= NNODES) return;
    int s0 = g_off[d], s1 = g_off[d + 1];
    for (int i = s0 + 1; i < s1; i++) {
        int v = g_eid[i];
        int j = i - 1;
        while (j >= s0 && g_eid[j] > v) { g_eid[j + 1] = g_eid[j]; j--; }
        g_eid[j + 1] = v;
    }
}

// ---------------- fp16 tensor-core GEMM ----------------
// Block 128x128, 4 warps (2x2), warp tile 64x64.  K-tile 64, 3-stage cp.async, ldmatrix.
// XOR-swizzled smem rows of exactly 128B.
// ONE barrier per K-iteration: the leading sync (post wait_group) already orders
// iteration t-1's reads of stage (t+2)%3 before load_tile(t+2) overwrites it.
#define KT 64
#define HG_OPH  (128 * KT)
#define HG_STG  (2 * HG_OPH)
#define HG_SMEM (3 * HG_STG * 2)           // 98304 bytes

__device__ __forceinline__ int sw_off(int r, int c) {
    return r * KT + ((c ^ (r & 7)) << 3);
}

__global__ void __launch_bounds__(128, 2)
hgemm(const __half* __restrict__ A, const __half* __restrict__ Bt,
      float* __restrict__ Cf, __half* __restrict__ Ch,
      int lda, int kLen, int N)
{
    extern __shared__ __half hs[];

    const int tid = threadIdx.x, wid = tid >> 5, lane = tid & 31;
    const int bn = blockIdx.x, bm = blockIdx.y, bz = blockIdx.z;
    const int k0 = bz * kLen;
    const int wm = (wid & 1) * 64;
    const int wn = (wid >> 1) * 64;
    const int g = lane >> 2, tg = lane & 3;

    const __half* Ag = A + (size_t)(bm * 128) * lda + k0;
    const __half* Bg = Bt + (size_t)(bn * 128) * lda + k0;

    float acc[32][4] = {};
    const int T = kLen / KT;

    auto load_tile = [&](int t) {
        int st = t % 3;
        __half* As = hs + st * HG_STG;
        __half* Bs = As + HG_OPH;
        int kk = t * KT;
#pragma unroll
        for (int i = 0; i < 8; i++) {
            int ci = tid + i * 128;
            int r = ci >> 3, c = ci & 7;
            int off = sw_off(r, c);
            const size_t go = (size_t)r * lda + kk + c * 8;
            cp16(smem_u32(&As[off]), Ag + go);
            cp16(smem_u32(&Bs[off]), Bg + go);
        }
        asm volatile("cp.async.commit_group;");
    };

    load_tile(0);
    if (T > 1) load_tile(1);

    const int a_r = lane & 15;
    const int a_c = lane >> 4;
    const int b_r = ((lane >> 4) << 3) + (lane & 7);
    const int b_c = (lane >> 3) & 1;

    for (int t = 0; t < T; t++) {
        asm volatile("cp.async.wait_group 1;");
        __syncthreads();
        if (t + 2 < T) load_tile(t + 2);

        const __half* Ab = hs + (t % 3) * HG_STG;
        const __half* Bb = Ab + HG_OPH;
#pragma unroll
        for (int kc = 0; kc < 4; kc++) {
            uint32_t a[4][4], b[8][2];
#pragma unroll
            for (int mi = 0; mi < 4; mi++) {
                uint32_t ad = smem_u32(&Ab[sw_off(wm + mi * 16 + a_r, kc * 2 + a_c)]);
                LDSM_X4(a[mi], ad);
            }
#pragma unroll
            for (int p = 0; p < 4; p++) {
                uint32_t br[4];
                uint32_t bd = smem_u32(&Bb[sw_off(wn + p * 16 + b_r, kc * 2 + b_c)]);
                LDSM_X4(br, bd);
                b[2 * p][0] = br[0]; b[2 * p][1] = br[1];
                b[2 * p + 1][0] = br[2]; b[2 * p + 1][1] = br[3];
            }
#pragma unroll
            for (int mi = 0; mi < 4; mi++)
#pragma unroll
                for (int ni = 0; ni < 8; ni++)
                    MMA_F16(acc[mi * 8 + ni], a[mi], b[ni]);
        }
        // no trailing __syncthreads: next iteration's leading barrier covers the
        // stage-reuse hazard (3-stage ring, load target differs from both live stages)
    }

    if (Ch) {
#pragma unroll
        for (int mi = 0; mi < 4; mi++) {
            int r0 = bm * 128 + wm + mi * 16 + g;
#pragma unroll
            for (int ni = 0; ni < 8; ni++) {
                int c = bn * 128 + wn + ni * 8 + tg * 2;
                __half* p = Ch + (size_t)r0 * N + c;
                __half2 v0 = __floats2half2_rn(acc[mi * 8 + ni][0], acc[mi * 8 + ni][1]);
                __half2 v1 = __floats2half2_rn(acc[mi * 8 + ni][2], acc[mi * 8 + ni][3]);
                *(__half2*)p = v0;
                *(__half2*)(p + (size_t)8 * N) = v1;
            }
        }
    } else {
        float* Cp = Cf + (size_t)bz * NNODES * DHID;
#pragma unroll
        for (int mi = 0; mi < 4; mi++) {
            int r0 = bm * 128 + wm + mi * 16 + g;
#pragma unroll
            for (int ni = 0; ni < 8; ni++) {
                int c = bn * 128 + wn + ni * 8 + tg * 2;
                float* p = Cp + (size_t)r0 * N + c;
                *(float2*)p = make_float2(acc[mi * 8 + ni][0], acc[mi * 8 + ni][1]);
                *(float2*)(p + (size_t)8 * N) = make_float2(acc[mi * 8 + ni][2], acc[mi * 8 + ni][3]);
            }
        }
    }
}

// ---------------- per-(node,head) attention coefficients (fp16 h) ----------------
__global__ void alphas_h_kernel(const __half* __restrict__ h,
                                const float* __restrict__ a_s, const float* __restrict__ a_d,
                                float* __restrict__ out_s, float* __restrict__ out_d,
                                int H, int C)
{
    int w = (blockIdx.x * blockDim.x + threadIdx.x) >> 5;
    int lane = threadIdx.x & 31;
    if (w >= NNODES * H) return;
    int n = w / H, hd = w % H;
    const __half* hp = h + (size_t)n * H * C + (size_t)hd * C;
    const float* asp = a_s + (size_t)hd * C;
    const float* adp = a_d + (size_t)hd * C;
    float ss = 0.f, sd = 0.f;
    for (int c = lane; c < C; c += 32) {
        float v = __half2float(hp[c]);
        ss += v * asp[c];
        sd += v * adp[c];
    }
#pragma unroll
    for (int o = 16; o; o >>= 1) {
        ss += __shfl_down_sync(0xffffffffu, ss, o);
        sd += __shfl_down_sync(0xffffffffu, sd, o);
    }
    if (lane == 0) { out_s[w] = ss; out_d[w] = sd; }
}

// ---------------- split-K reduce + layer-2 alphas (fused) ----------------
__global__ void reduce_alphas2_kernel(const float* __restrict__ part,
                                      float* __restrict__ h2,
                                      const float* __restrict__ a_s, const float* __restrict__ a_d,
                                      float* __restrict__ out_s, float* __restrict__ out_d)
{
    int w = (blockIdx.x * blockDim.x + threadIdx.x) >> 5;
    int lane = threadIdx.x & 31;
    if (w >= NNODES) return;
    const size_t base = (size_t)w * DHID;
    const size_t pstride = (size_t)NNODES * DHID;
    float ss = 0.f, sd = 0.f;
    for (int c = lane; c < DHID; c += 32) {
        float s = part[base + c] + part[pstride + base + c] + part[2 * pstride + base + c];
        h2[base + c] = s;
        ss += s * a_s[c];
        sd += s * a_d[c];
    }
#pragma unroll
    for (int o = 16; o; o >>= 1) {
        ss += __shfl_down_sync(0xffffffffu, ss, o);
        sd += __shfl_down_sync(0xffffffffu, sd, o);
    }
    if (lane == 0) { out_s[w] = ss; out_d[w] = sd; }
}

// ---------------- per-(dst,head) segment softmax ----------------
__global__ void softmax_kernel(const int* __restrict__ src,
                               const float* __restrict__ as, const float* __restrict__ ad,
                               float* __restrict__ alpha, int H)
{
    int idx = blockIdx.x * blockDim.x + threadIdx.x;
    if (idx >= NNODES * H) return;
    int d = idx / H, hd = idx % H;
    int s0 = g_off[d], s1 = g_off[d + 1];
    if (s0 == s1) return;
    float adv = ad[idx];

    float m = -1e30f;
    for (int i = s0; i < s1; i++) {
        int e = g_eid[i];
        float x = as[src[e] * H + hd] + adv;
        x = (x > 0.f) ? x : NEG_SLOPE * x;
        m = fmaxf(m, x);
    }
    float sum = 0.f;
    for (int i = s0; i < s1; i++) {
        int e = g_eid[i];
        float x = as[src[e] * H + hd] + adv;
        x = (x > 0.f) ? x : NEG_SLOPE * x;
        float w = __expf(x - m);
        alpha[(size_t)e * H + hd] = w;
        sum += w;
    }
    float inv = 1.f / (sum + EPSV);
    for (int i = s0; i < s1; i++) {
        int e = g_eid[i];
        alpha[(size_t)e * H + hd] *= inv;
    }
}

// ---------------- layer-1 aggregation: one block per node, all heads ----------------
__global__ void __launch_bounds__(256)
aggregate1_kernel(const int* __restrict__ src, const float* __restrict__ alpha,
                  const __half* __restrict__ h, __half* __restrict__ out_h,
                  const float* __restrict__ bias)
{
    int d  = blockIdx.x;
    int t  = threadIdx.x;
    int hd = t >> 5;
    size_t rowoff = (size_t)hd * DHID + (size_t)(t & 31) * 24;
    int s0 = g_off[d], s1 = g_off[d + 1];
    const size_t rs = (size_t)H1N * DHID;

    float acc[24];
#pragma unroll
    for (int j = 0; j < 24; j++) acc[j] = 0.f;

    for (int i = s0; i < s1; i++) {
        int e = g_eid[i];
        float a = alpha[(size_t)e * H1N + hd];
        const uint4* p = (const uint4*)(h + (size_t)src[e] * rs + rowoff);
#pragma unroll
        for (int j = 0; j < 3; j++) {
            uint4 u = p[j];
            const __half2* hh = (const __half2*)&u;
#pragma unroll
            for (int k = 0; k < 4; k++) {
                float2 f = __half22float2(hh[k]);
                acc[j * 8 + k * 2]     += a * f.x;
                acc[j * 8 + k * 2 + 1] += a * f.y;
            }
        }
    }

    const float* bp = bias + rowoff;
    __half* op = out_h + (size_t)d * rs + rowoff;
#pragma unroll
    for (int j = 0; j < 3; j++) {
        uint4 u;
        __half2* hh = (__half2*)&u;
#pragma unroll
        for (int k = 0; k < 4; k++) {
            float v0 = acc[j * 8 + k * 2]     + bp[j * 8 + k * 2];
            float v1 = acc[j * 8 + k * 2 + 1] + bp[j * 8 + k * 2 + 1];
            v0 = (v0 > 0.f) ? v0 : expm1f(v0);
            v1 = (v1 > 0.f) ? v1 : expm1f(v1);
            hh[k] = __floats2half2_rn(v0, v1);
        }
        ((uint4*)op)[j] = u;
    }
}

// ---------------- layer-2 aggregation: fp32 gather, fp32 out ----------------
__global__ void __launch_bounds__(192)
aggregate2_kernel(const int* __restrict__ src, const float* __restrict__ alpha,
                  const float* __restrict__ h, float* __restrict__ out,
                  const float* __restrict__ bias)
{
    int d = blockIdx.x;
    int t = threadIdx.x;
    int s0 = g_off[d], s1 = g_off[d + 1];

    float4 acc = make_float4(0.f, 0.f, 0.f, 0.f);
    for (int i = s0; i < s1; i++) {
        int e = g_eid[i];
        float a = alpha[e];
        float4 v = *(((const float4*)(h + (size_t)src[e] * DHID)) + t);
        acc.x += a * v.x; acc.y += a * v.y; acc.z += a * v.z; acc.w += a * v.w;
    }
    float4 b = *(((const float4*)bias) + t);
    acc.x += b.x; acc.y += b.y; acc.z += b.z; acc.w += b.w;
    *(((float4*)(out + (size_t)d * DHID)) + t) = acc;
}

// ---------------- launch ----------------
extern "C" void kernel_launch(void* const* d_in, const int* in_sizes, int n_in,
                              void* d_out, int out_size)
{
    const float* x    = (const float*)d_in[0];
    const float* W1   = (const float*)d_in[1];
    const float* a_s1 = (const float*)d_in[2];
    const float* a_d1 = (const float*)d_in[3];
    const float* b1   = (const float*)d_in[4];
    const float* W2   = (const float*)d_in[5];
    const float* a_s2 = (const float*)d_in[6];
    const float* a_d2 = (const float*)d_in[7];
    const float* b2   = (const float*)d_in[8];
    const int* edges  = (const int*)d_in[9];
    const int* src = edges;
    const int* dst = edges + NEDGES;
    float* out = (float*)d_out;

    float *part, *h2, *as1, *ad1, *as2, *ad2, *al1, *al2;
    __half *h1h, *xh, *o1h, *w1th, *w2th;
    cudaGetSymbolAddress((void**)&h1h,  g_h1h);
    cudaGetSymbolAddress((void**)&part, g_part);
    cudaGetSymbolAddress((void**)&h2,   g_h2);
    cudaGetSymbolAddress((void**)&xh,   g_xh);
    cudaGetSymbolAddress((void**)&o1h,  g_o1h);
    cudaGetSymbolAddress((void**)&w1th, g_w1th);
    cudaGetSymbolAddress((void**)&w2th, g_w2th);
    cudaGetSymbolAddress((void**)&as1,  g_as1);
    cudaGetSymbolAddress((void**)&ad1,  g_ad1);
    cudaGetSymbolAddress((void**)&as2,  g_as2);
    cudaGetSymbolAddress((void**)&ad2,  g_ad2);
    cudaGetSymbolAddress((void**)&al1,  g_alpha1);
    cudaGetSymbolAddress((void**)&al2,  g_alpha2);

    cudaFuncSetAttribute(hgemm, cudaFuncAttributeMaxDynamicSharedMemorySize, HG_SMEM);

    // Streams/events created once on the (uncaptured) first call.
    static cudaStream_t s2 = nullptr, s3 = nullptr;
    static cudaEvent_t evFork = nullptr, evJoin2 = nullptr, evJoin3 = nullptr;
    if (!s2) {
        cudaStreamCreateWithFlags(&s2, cudaStreamNonBlocking);
        cudaStreamCreateWithFlags(&s3, cudaStreamNonBlocking);
        cudaEventCreateWithFlags(&evFork,  cudaEventDisableTiming);
        cudaEventCreateWithFlags(&evJoin2, cudaEventDisableTiming);
        cudaEventCreateWithFlags(&evJoin3, cudaEventDisableTiming);
    }

    dim3 tblk(32, 8);

    // ---- fork ----
    cudaEventRecord(evFork, 0);
    cudaStreamWaitEvent(s2, evFork, 0);
    cudaStreamWaitEvent(s3, evFork, 0);

    // s2: CSR chain + W2 transpose (needed at softmax1 / GEMM2)
    zero_counts_kernel<<<(NNODES + 255) / 256, 256, 0, s2>>>();
    count_kernel<<<(NEDGES + 255) / 256, 256, 0, s2>>>(dst);
    scan_kernel<<<1, 1024, 0, s2>>>();
    scatter_kernel<<<(NEDGES + 255) / 256, 256, 0, s2>>>(dst);
    sort_eid_kernel<<<(NNODES + 255) / 256, 256, 0, s2>>>();
    {
        dim3 gt(DHID / 32, (H1N * DHID) / 32);
        transpose_h_kernel<<<gt, tblk, 0, s2>>>(W2, w2th, H1N * DHID, DHID);
    }
    cudaEventRecord(evJoin2, s2);

    // s3: W1 transpose (needed at GEMM1)
    {
        dim3 gt((H1N * DHID) / 32, DIN / 32);
        transpose_h_kernel<<<gt, tblk, 0, s3>>>(W1, w1th, DIN, H1N * DHID);
    }
    cudaEventRecord(evJoin3, s3);

    // ---- main chain ----
    f2h_kernel<<<(NNODES * DIN / 4 + 255) / 256, 256>>>(x, xh, NNODES * DIN / 4);
    cudaStreamWaitEvent(0, evJoin3, 0);
    {
        dim3 grid((H1N * DHID) / 128, NNODES / 128, 1);   // (48, 64)
        hgemm<<<grid, 128, HG_SMEM>>>(xh, w1th, nullptr, h1h, DIN, DIN, H1N * DHID);
    }
    alphas_h_kernel<<<(NNODES * H1N * 32 + 255) / 256, 256>>>(h1h, a_s1, a_d1, as1, ad1, H1N, DHID);

    cudaStreamWaitEvent(0, evJoin2, 0);

    softmax_kernel<<<(NNODES * H1N + 255) / 256, 256>>>(src, as1, ad1, al1, H1N);
    aggregate1_kernel<<<NNODES, 256>>>(src, al1, h1h, o1h, b1);
    {
        dim3 grid((H2N * DHID) / 128, NNODES / 128, SPLITK);   // (6, 64, 3)
        hgemm<<<grid, 128, HG_SMEM>>>(o1h, w2th, part, nullptr, H1N * DHID, K2CHUNK, H2N * DHID);
    }
    reduce_alphas2_kernel<<<(NNODES * 32 + 255) / 256, 256>>>(part, h2, a_s2, a_d2, as2, ad2);
    softmax_kernel<<<(NNODES + 255) / 256, 256>>>(src, as2, ad2, al2, H2N);
    aggregate2_kernel<<<NNODES, DHID / 4>>>(src, al2, h2, out, b2);
}